// round 6
// baseline (speedup 1.0000x reference)
#include <cuda_runtime.h>
#include <cstdint>

#define BB 8
#define C_IN 64
#define C_OUT 128
#define HH 256
#define WW 256
#define NK 8

#define TH 16
#define TW 64
#define COT 16          // c_out per block (8 warps x 2 each)
#define SROW 68         // padded smem row stride (floats)
#define CPR 2           // channels per round

__device__ float g_pooled[BB * C_IN];
__device__ float g_attn[BB * NK];
__device__ float g_mixed[BB * C_OUT * C_IN * 9];

typedef unsigned long long ull;

__device__ __forceinline__ ull pk(float lo, float hi) {
    ull r;
    asm("mov.b64 %0, {%1, %2};" : "=l"(r) : "f"(lo), "f"(hi));
    return r;
}
__device__ __forceinline__ void upk(float& lo, float& hi, ull v) {
    asm("mov.b64 {%0, %1}, %2;" : "=f"(lo), "=f"(hi) : "l"(v));
}
__device__ __forceinline__ ull ffma2(ull a, ull b, ull c) {
    ull d;
    asm("fma.rn.f32x2 %0, %1, %2, %3;" : "=l"(d) : "l"(a), "l"(b), "l"(c));
    return d;
}

// ---------------- Kernel 1: global average pool per (b, c_in) ----------------
__global__ void pool_kernel(const float* __restrict__ x) {
    int idx = blockIdx.x;  // b*C_IN + ci
    const float4* p = reinterpret_cast<const float4*>(x + (size_t)idx * (HH * WW));
    float s = 0.f;
    for (int i = threadIdx.x; i < (HH * WW) / 4; i += blockDim.x) {
        float4 v = p[i];
        s += v.x + v.y + v.z + v.w;
    }
    __shared__ float red[256];
    red[threadIdx.x] = s;
    __syncthreads();
    for (int off = 128; off > 0; off >>= 1) {
        if (threadIdx.x < off) red[threadIdx.x] += red[threadIdx.x + off];
        __syncthreads();
    }
    if (threadIdx.x == 0) g_pooled[idx] = red[0] * (1.0f / (HH * WW));
}

// ---------------- Kernel 2: logits + softmax -> attention weights ----------------
__global__ void attn_kernel(const float* __restrict__ attn_w,
                            const float* __restrict__ attn_b) {
    __shared__ float lg[BB * NK];
    int t = threadIdx.x;
    if (t < BB * NK) {
        int b = t / NK, n = t % NK;
        float s = attn_b[n];
        #pragma unroll 8
        for (int c = 0; c < C_IN; c++) s += g_pooled[b * C_IN + c] * attn_w[n * C_IN + c];
        lg[t] = s;
    }
    __syncthreads();
    if (t < BB) {
        float m = -1e30f;
        for (int n = 0; n < NK; n++) m = fmaxf(m, lg[t * NK + n]);
        float e[NK];
        float sum = 0.f;
        for (int n = 0; n < NK; n++) { e[n] = expf(lg[t * NK + n] - m); sum += e[n]; }
        float inv = 1.0f / sum;
        for (int n = 0; n < NK; n++) g_attn[t * NK + n] = e[n] * inv;
    }
}

// ---------------- Kernel 3: mix kernel bank by attention ----------------
__global__ void mix_kernel(const float* __restrict__ bank) {
    const int R = C_OUT * C_IN * 9;
    int i = blockIdx.x * blockDim.x + threadIdx.x;
    if (i >= BB * R) return;
    int b = i / R, r = i - b * R;
    float s = 0.f;
    #pragma unroll
    for (int n = 0; n < NK; n++) s += g_attn[b * NK + n] * bank[(size_t)n * R + r];
    g_mixed[i] = s;
}

// ---------------- Kernel 4: conv, f32x2 FMA, MOV-free inner loop ----------
// Block: 256 threads = 8 warps; tile 64x16, 16 c_out (2 per warp).
// Lane owns adjacent output cols (2l, 2l+1) packed in one f32x2.
// Smem row layout: idx = col+1, so p0 (cols 2l-1,2l) sits at even idx 2l and
// p2 (cols 2l+1,2l+2) at even idx 2l+2 -> both are single aligned LDS.64
// loaded DIRECTLY into 64-bit regs (no MOV packing). p1 = {hi(p0), lo(p2)}
// costs 2 MOVs/row. Weights are staged in smem pre-duplicated as (w,w) ull
// pairs -> weight setup per ci is 18 LDS.64, zero MOVs.
// Register-staged double buffering hides gmem latency (loop-invariant plan).
__global__ void __launch_bounds__(256, 2) conv_kernel(const float* __restrict__ x,
                                                      float* __restrict__ out) {
    __shared__ float sx[CPR][TH + 2][SROW];
    __shared__ ull swt[CPR][COT][9];

    const int tid = threadIdx.x;
    const int lane = tid & 31;
    const int wrp = tid >> 5;
    const int gx0 = blockIdx.x * TW;
    const int gy0 = blockIdx.y * TH;
    const int bz = blockIdx.z;            // b * (C_OUT/COT) + cog
    const int b = bz >> 3;                // C_OUT/COT = 8
    const int cobase = (bz & 7) * COT;

    const float* xb = x + (size_t)b * C_IN * (HH * WW);

    // ---- loop-invariant load plan ----
    // interior: 2ch x 18rows x 16 float4 = 576 slots
    int g_off[3]; bool g_val[3]; float* s_dst[3]; int g_ch[3];
    #pragma unroll
    for (int s = 0; s < 3; s++) {
        int i = tid + s * 256;
        g_val[s] = false; g_off[s] = 0; g_ch[s] = 0; s_dst[s] = &sx[0][0][0];
        if (i < 576) {
            int ch = i / 288, k = i - ch * 288;
            int rr = k >> 4, c4 = k & 15;
            int y = gy0 + rr - 1;
            g_ch[s] = ch;
            g_val[s] = (y >= 0) && (y < HH);
            g_off[s] = (g_val[s] ? y : 0) * WW + gx0 + c4 * 4;
            s_dst[s] = &sx[ch][rr][1 + c4 * 4];
        }
    }
    // halo cols: 2ch x 18rows x 2 = 72 slots
    bool h_act = tid < 72, h_val = false;
    int h_off = 0, h_ch = 0; float* h_dst = &sx[0][0][0];
    if (h_act) {
        int ch = tid / 36, k = tid - ch * 36;
        int r = k >> 1, side = k & 1;
        int y = gy0 + r - 1;
        int xc = side ? gx0 + 64 : gx0 - 1;
        h_ch = ch;
        h_val = (y >= 0) && (y < HH) && (xc >= 0) && (xc < WW);
        h_off = (h_val ? y * WW + xc : 0);
        h_dst = &sx[ch][r][side ? 65 : 0];
    }
    // weights: 2ch x 16cout x 9 = 288 slots; thread t does t and (t<32) t+256
    ull* wflat = &swt[0][0][0];
    const float* w_src0;
    const float* w_src1 = nullptr;
    {
        int idx = tid;
        int ci2 = idx / 144, k = idx - ci2 * 144, col = k / 9, t = k - col * 9;
        w_src0 = g_mixed + (((size_t)b * C_OUT + cobase + col) * C_IN + ci2) * 9 + t;
        if (tid < 32) {
            idx = tid + 256;
            ci2 = idx / 144; k = idx - ci2 * 144; col = k / 9; t = k - col * 9;
            w_src1 = g_mixed + (((size_t)b * C_OUT + cobase + col) * C_IN + ci2) * 9 + t;
        }
    }

    ull accA[TH], accB[TH];
    #pragma unroll
    for (int i = 0; i < TH; i++) { accA[i] = 0ULL; accB[i] = 0ULL; }

    float4 rI[3]; float rH = 0.f, rw0 = 0.f, rw1 = 0.f;

    // preload round 0 (ci = 0)
    #pragma unroll
    for (int s = 0; s < 3; s++) {
        rI[s] = make_float4(0.f, 0.f, 0.f, 0.f);
        if (g_val[s])
            rI[s] = *reinterpret_cast<const float4*>(xb + (size_t)g_ch[s] * (HH * WW) + g_off[s]);
    }
    if (h_val) rH = xb[(size_t)h_ch * (HH * WW) + h_off];
    rw0 = *w_src0;
    if (tid < 32) rw1 = *w_src1;

    const int ROUNDS = C_IN / CPR;   // 32
    for (int rd = 0; rd < ROUNDS; rd++) {
        __syncthreads();   // previous compute done; safe to overwrite smem
        // stage registers -> smem (weights stored pre-duplicated as (w,w))
        #pragma unroll
        for (int s = 0; s < 3; s++) {
            if (tid + s * 256 < 576) {
                s_dst[s][0] = rI[s].x; s_dst[s][1] = rI[s].y;
                s_dst[s][2] = rI[s].z; s_dst[s][3] = rI[s].w;
            }
        }
        if (h_act) *h_dst = rH;
        wflat[tid] = pk(rw0, rw0);
        if (tid < 32) wflat[256 + tid] = pk(rw1, rw1);
        __syncthreads();

        // prefetch next round into registers (hidden behind compute)
        if (rd + 1 < ROUNDS) {
            int ci = (rd + 1) * CPR;
            #pragma unroll
            for (int s = 0; s < 3; s++) {
                if (tid + s * 256 < 576) {
                    float4 v = make_float4(0.f, 0.f, 0.f, 0.f);
                    if (g_val[s])
                        v = *reinterpret_cast<const float4*>(
                            xb + (size_t)(ci + g_ch[s]) * (HH * WW) + g_off[s]);
                    rI[s] = v;
                }
            }
            if (h_val) rH = xb[(size_t)(ci + h_ch) * (HH * WW) + h_off];
            rw0 = w_src0[ci * 9];
            if (tid < 32) rw1 = w_src1[ci * 9];
        }

        // compute the two staged channels
        #pragma unroll
        for (int ci2 = 0; ci2 < CPR; ci2++) {
            // weights: direct LDS.64 of pre-duplicated pairs, no MOVs
            ull wA[9], wB[9];
            const ull* wpA = &swt[ci2][wrp][0];
            const ull* wpB = &swt[ci2][wrp + 8][0];
            #pragma unroll
            for (int t = 0; t < 9; t++) { wA[t] = wpA[t]; wB[t] = wpB[t]; }

            #pragma unroll
            for (int r = 0; r < TH + 2; r++) {
                const ull* rowp = reinterpret_cast<const ull*>(&sx[ci2][r][0]);
                ull p0 = rowp[lane];         // cols (2l-1, 2l)   -- aligned LDS.64
                ull p2 = rowp[lane + 1];     // cols (2l+1, 2l+2) -- aligned LDS.64
                float p0lo, p0hi, p2lo, p2hi;
                upk(p0lo, p0hi, p0);         // free: register-half reads
                upk(p2lo, p2hi, p2);
                ull p1 = pk(p0hi, p2lo);     // 2 MOVs
                if (r < TH) {
                    accA[r] = ffma2(p0, wA[0], ffma2(p1, wA[1], ffma2(p2, wA[2], accA[r])));
                    accB[r] = ffma2(p0, wB[0], ffma2(p1, wB[1], ffma2(p2, wB[2], accB[r])));
                }
                if (r >= 1 && r - 1 < TH) {
                    accA[r-1] = ffma2(p0, wA[3], ffma2(p1, wA[4], ffma2(p2, wA[5], accA[r-1])));
                    accB[r-1] = ffma2(p0, wB[3], ffma2(p1, wB[4], ffma2(p2, wB[5], accB[r-1])));
                }
                if (r >= 2) {
                    accA[r-2] = ffma2(p0, wA[6], ffma2(p1, wA[7], ffma2(p2, wA[8], accA[r-2])));
                    accB[r-2] = ffma2(p0, wB[6], ffma2(p1, wB[7], ffma2(p2, wB[8], accB[r-2])));
                }
            }
        }
    }

    int co0 = cobase + wrp;
    int co1 = cobase + 8 + wrp;
    float* opA = out + (((size_t)b * C_OUT + co0) * HH + gy0) * WW + gx0 + 2 * lane;
    float* opB = out + (((size_t)b * C_OUT + co1) * HH + gy0) * WW + gx0 + 2 * lane;
    #pragma unroll
    for (int o = 0; o < TH; o++) {
        float lo, hi;
        upk(lo, hi, accA[o]);
        *reinterpret_cast<float2*>(&opA[o * WW]) = make_float2(lo, hi);
        upk(lo, hi, accB[o]);
        *reinterpret_cast<float2*>(&opB[o * WW]) = make_float2(lo, hi);
    }
}

extern "C" void kernel_launch(void* const* d_in, const int* in_sizes, int n_in,
                              void* d_out, int out_size) {
    const float* x    = (const float*)d_in[0];
    const float* bank = (const float*)d_in[1];
    const float* aw   = (const float*)d_in[2];
    const float* ab   = (const float*)d_in[3];
    float* out = (float*)d_out;

    pool_kernel<<<BB * C_IN, 256>>>(x);
    attn_kernel<<<1, 64>>>(aw, ab);
    mix_kernel<<<(BB * C_OUT * C_IN * 9 + 255) / 256, 256>>>(bank);

    dim3 g(WW / TW, HH / TH, BB * (C_OUT / COT));
    conv_kernel<<<g, 256>>>(x, out);
}

// round 7
// speedup vs baseline: 1.0043x; 1.0043x over previous
#include <cuda_runtime.h>
#include <cstdint>

#define BB 8
#define C_IN 64
#define C_OUT 128
#define HH 256
#define WW 256
#define NK 8

#define TH 16
#define TW 64
#define COT 16          // c_out per block (8 warps x 2 each)
#define SROW 68         // padded smem row stride (floats)
#define CPR 2           // channels per round

__device__ float g_pooled[BB * C_IN];
__device__ float g_attn[BB * NK];
__device__ float g_mixed[BB * C_OUT * C_IN * 9];

typedef unsigned long long ull;

__device__ __forceinline__ ull pk(float lo, float hi) {
    ull r;
    asm("mov.b64 %0, {%1, %2};" : "=l"(r) : "f"(lo), "f"(hi));
    return r;
}
__device__ __forceinline__ void upk(float& lo, float& hi, ull v) {
    asm("mov.b64 {%0, %1}, %2;" : "=f"(lo), "=f"(hi) : "l"(v));
}
__device__ __forceinline__ ull ffma2(ull a, ull b, ull c) {
    ull d;
    asm("fma.rn.f32x2 %0, %1, %2, %3;" : "=l"(d) : "l"(a), "l"(b), "l"(c));
    return d;
}

// ---------------- Kernel 1: global average pool per (b, c_in) ----------------
__global__ void pool_kernel(const float* __restrict__ x) {
    int idx = blockIdx.x;  // b*C_IN + ci
    const float4* p = reinterpret_cast<const float4*>(x + (size_t)idx * (HH * WW));
    float s = 0.f;
    for (int i = threadIdx.x; i < (HH * WW) / 4; i += blockDim.x) {
        float4 v = p[i];
        s += v.x + v.y + v.z + v.w;
    }
    __shared__ float red[256];
    red[threadIdx.x] = s;
    __syncthreads();
    for (int off = 128; off > 0; off >>= 1) {
        if (threadIdx.x < off) red[threadIdx.x] += red[threadIdx.x + off];
        __syncthreads();
    }
    if (threadIdx.x == 0) g_pooled[idx] = red[0] * (1.0f / (HH * WW));
}

// ---------------- Kernel 2: logits + softmax -> attention weights ----------------
__global__ void attn_kernel(const float* __restrict__ attn_w,
                            const float* __restrict__ attn_b) {
    __shared__ float lg[BB * NK];
    int t = threadIdx.x;
    if (t < BB * NK) {
        int b = t / NK, n = t % NK;
        float s = attn_b[n];
        #pragma unroll 8
        for (int c = 0; c < C_IN; c++) s += g_pooled[b * C_IN + c] * attn_w[n * C_IN + c];
        lg[t] = s;
    }
    __syncthreads();
    if (t < BB) {
        float m = -1e30f;
        for (int n = 0; n < NK; n++) m = fmaxf(m, lg[t * NK + n]);
        float e[NK];
        float sum = 0.f;
        for (int n = 0; n < NK; n++) { e[n] = expf(lg[t * NK + n] - m); sum += e[n]; }
        float inv = 1.0f / sum;
        for (int n = 0; n < NK; n++) g_attn[t * NK + n] = e[n] * inv;
    }
}

// ---------------- Kernel 3: mix kernel bank by attention ----------------
__global__ void mix_kernel(const float* __restrict__ bank) {
    const int R = C_OUT * C_IN * 9;
    int i = blockIdx.x * blockDim.x + threadIdx.x;
    if (i >= BB * R) return;
    int b = i / R, r = i - b * R;
    float s = 0.f;
    #pragma unroll
    for (int n = 0; n < NK; n++) s += g_attn[b * NK + n] * bank[(size_t)n * R + r];
    g_mixed[i] = s;
}

// ---------------- Kernel 4: conv, f32x2 FMA, MOV-free inner loop ----------
// Block: 256 threads = 8 warps; tile 64x16, 16 c_out (2 per warp).
// Lane owns adjacent output cols (2l, 2l+1) packed in one f32x2.
// Smem row layout: idx = col+1, so p0 (cols 2l-1,2l) sits at even idx 2l and
// p2 (cols 2l+1,2l+2) at even idx 2l+2 -> both are single aligned LDS.64
// loaded DIRECTLY into 64-bit regs (no MOV packing). p1 = {hi(p0), lo(p2)}
// costs 2 MOVs/row. Weights are staged in smem pre-duplicated as (w,w) ull
// pairs -> weight setup per ci is 18 LDS.64, zero MOVs.
// Register-staged double buffering hides gmem latency (loop-invariant plan).
__global__ void __launch_bounds__(256, 2) conv_kernel(const float* __restrict__ x,
                                                      float* __restrict__ out) {
    __shared__ float sx[CPR][TH + 2][SROW];
    __shared__ ull swt[CPR][COT][9];

    const int tid = threadIdx.x;
    const int lane = tid & 31;
    const int wrp = tid >> 5;
    const int gx0 = blockIdx.x * TW;
    const int gy0 = blockIdx.y * TH;
    const int bz = blockIdx.z;            // b * (C_OUT/COT) + cog
    const int b = bz >> 3;                // C_OUT/COT = 8
    const int cobase = (bz & 7) * COT;

    const float* xb = x + (size_t)b * C_IN * (HH * WW);

    // ---- loop-invariant load plan ----
    // interior: 2ch x 18rows x 16 float4 = 576 slots
    int g_off[3]; bool g_val[3]; float* s_dst[3]; int g_ch[3];
    #pragma unroll
    for (int s = 0; s < 3; s++) {
        int i = tid + s * 256;
        g_val[s] = false; g_off[s] = 0; g_ch[s] = 0; s_dst[s] = &sx[0][0][0];
        if (i < 576) {
            int ch = i / 288, k = i - ch * 288;
            int rr = k >> 4, c4 = k & 15;
            int y = gy0 + rr - 1;
            g_ch[s] = ch;
            g_val[s] = (y >= 0) && (y < HH);
            g_off[s] = (g_val[s] ? y : 0) * WW + gx0 + c4 * 4;
            s_dst[s] = &sx[ch][rr][1 + c4 * 4];
        }
    }
    // halo cols: 2ch x 18rows x 2 = 72 slots
    bool h_act = tid < 72, h_val = false;
    int h_off = 0, h_ch = 0; float* h_dst = &sx[0][0][0];
    if (h_act) {
        int ch = tid / 36, k = tid - ch * 36;
        int r = k >> 1, side = k & 1;
        int y = gy0 + r - 1;
        int xc = side ? gx0 + 64 : gx0 - 1;
        h_ch = ch;
        h_val = (y >= 0) && (y < HH) && (xc >= 0) && (xc < WW);
        h_off = (h_val ? y * WW + xc : 0);
        h_dst = &sx[ch][r][side ? 65 : 0];
    }
    // weights: 2ch x 16cout x 9 = 288 slots; thread t does t and (t<32) t+256
    ull* wflat = &swt[0][0][0];
    const float* w_src0;
    const float* w_src1 = nullptr;
    {
        int idx = tid;
        int ci2 = idx / 144, k = idx - ci2 * 144, col = k / 9, t = k - col * 9;
        w_src0 = g_mixed + (((size_t)b * C_OUT + cobase + col) * C_IN + ci2) * 9 + t;
        if (tid < 32) {
            idx = tid + 256;
            ci2 = idx / 144; k = idx - ci2 * 144; col = k / 9; t = k - col * 9;
            w_src1 = g_mixed + (((size_t)b * C_OUT + cobase + col) * C_IN + ci2) * 9 + t;
        }
    }

    ull accA[TH], accB[TH];
    #pragma unroll
    for (int i = 0; i < TH; i++) { accA[i] = 0ULL; accB[i] = 0ULL; }

    float4 rI[3]; float rH = 0.f, rw0 = 0.f, rw1 = 0.f;

    // preload round 0 (ci = 0)
    #pragma unroll
    for (int s = 0; s < 3; s++) {
        rI[s] = make_float4(0.f, 0.f, 0.f, 0.f);
        if (g_val[s])
            rI[s] = *reinterpret_cast<const float4*>(xb + (size_t)g_ch[s] * (HH * WW) + g_off[s]);
    }
    if (h_val) rH = xb[(size_t)h_ch * (HH * WW) + h_off];
    rw0 = *w_src0;
    if (tid < 32) rw1 = *w_src1;

    const int ROUNDS = C_IN / CPR;   // 32
    for (int rd = 0; rd < ROUNDS; rd++) {
        __syncthreads();   // previous compute done; safe to overwrite smem
        // stage registers -> smem (weights stored pre-duplicated as (w,w))
        #pragma unroll
        for (int s = 0; s < 3; s++) {
            if (tid + s * 256 < 576) {
                s_dst[s][0] = rI[s].x; s_dst[s][1] = rI[s].y;
                s_dst[s][2] = rI[s].z; s_dst[s][3] = rI[s].w;
            }
        }
        if (h_act) *h_dst = rH;
        wflat[tid] = pk(rw0, rw0);
        if (tid < 32) wflat[256 + tid] = pk(rw1, rw1);
        __syncthreads();

        // prefetch next round into registers (hidden behind compute)
        if (rd + 1 < ROUNDS) {
            int ci = (rd + 1) * CPR;
            #pragma unroll
            for (int s = 0; s < 3; s++) {
                if (tid + s * 256 < 576) {
                    float4 v = make_float4(0.f, 0.f, 0.f, 0.f);
                    if (g_val[s])
                        v = *reinterpret_cast<const float4*>(
                            xb + (size_t)(ci + g_ch[s]) * (HH * WW) + g_off[s]);
                    rI[s] = v;
                }
            }
            if (h_val) rH = xb[(size_t)(ci + h_ch) * (HH * WW) + h_off];
            rw0 = w_src0[ci * 9];
            if (tid < 32) rw1 = w_src1[ci * 9];
        }

        // compute the two staged channels
        #pragma unroll
        for (int ci2 = 0; ci2 < CPR; ci2++) {
            // weights: direct LDS.64 of pre-duplicated pairs, no MOVs
            ull wA[9], wB[9];
            const ull* wpA = &swt[ci2][wrp][0];
            const ull* wpB = &swt[ci2][wrp + 8][0];
            #pragma unroll
            for (int t = 0; t < 9; t++) { wA[t] = wpA[t]; wB[t] = wpB[t]; }

            #pragma unroll
            for (int r = 0; r < TH + 2; r++) {
                const ull* rowp = reinterpret_cast<const ull*>(&sx[ci2][r][0]);
                ull p0 = rowp[lane];         // cols (2l-1, 2l)   -- aligned LDS.64
                ull p2 = rowp[lane + 1];     // cols (2l+1, 2l+2) -- aligned LDS.64
                float p0lo, p0hi, p2lo, p2hi;
                upk(p0lo, p0hi, p0);         // free: register-half reads
                upk(p2lo, p2hi, p2);
                ull p1 = pk(p0hi, p2lo);     // 2 MOVs
                if (r < TH) {
                    accA[r] = ffma2(p0, wA[0], ffma2(p1, wA[1], ffma2(p2, wA[2], accA[r])));
                    accB[r] = ffma2(p0, wB[0], ffma2(p1, wB[1], ffma2(p2, wB[2], accB[r])));
                }
                if (r >= 1 && r - 1 < TH) {
                    accA[r-1] = ffma2(p0, wA[3], ffma2(p1, wA[4], ffma2(p2, wA[5], accA[r-1])));
                    accB[r-1] = ffma2(p0, wB[3], ffma2(p1, wB[4], ffma2(p2, wB[5], accB[r-1])));
                }
                if (r >= 2) {
                    accA[r-2] = ffma2(p0, wA[6], ffma2(p1, wA[7], ffma2(p2, wA[8], accA[r-2])));
                    accB[r-2] = ffma2(p0, wB[6], ffma2(p1, wB[7], ffma2(p2, wB[8], accB[r-2])));
                }
            }
        }
    }

    int co0 = cobase + wrp;
    int co1 = cobase + 8 + wrp;
    float* opA = out + (((size_t)b * C_OUT + co0) * HH + gy0) * WW + gx0 + 2 * lane;
    float* opB = out + (((size_t)b * C_OUT + co1) * HH + gy0) * WW + gx0 + 2 * lane;
    #pragma unroll
    for (int o = 0; o < TH; o++) {
        float lo, hi;
        upk(lo, hi, accA[o]);
        *reinterpret_cast<float2*>(&opA[o * WW]) = make_float2(lo, hi);
        upk(lo, hi, accB[o]);
        *reinterpret_cast<float2*>(&opB[o * WW]) = make_float2(lo, hi);
    }
}

extern "C" void kernel_launch(void* const* d_in, const int* in_sizes, int n_in,
                              void* d_out, int out_size) {
    const float* x    = (const float*)d_in[0];
    const float* bank = (const float*)d_in[1];
    const float* aw   = (const float*)d_in[2];
    const float* ab   = (const float*)d_in[3];
    float* out = (float*)d_out;

    pool_kernel<<<BB * C_IN, 256>>>(x);
    attn_kernel<<<1, 64>>>(aw, ab);
    mix_kernel<<<(BB * C_OUT * C_IN * 9 + 255) / 256, 256>>>(bank);

    dim3 g(WW / TW, HH / TH, BB * (C_OUT / COT));
    conv_kernel<<<g, 256>>>(x, out);
}

// round 9
// speedup vs baseline: 1.7376x; 1.7301x over previous
#include <cuda_runtime.h>
#include <cuda_bf16.h>
#include <cstdint>

#define BB 8
#define C_IN 64
#define C_OUT 128
#define HH 256
#define WW 256
#define NK 8

#define APITCH 72            // bf16 elems per smem row (144B, conflict-free ldmatrix)
#define AROWS 396            // 3 y-blocks x 132 x-halo entries
#define WROWS 128

__device__ float g_pooled[BB * C_IN];
__device__ float g_attn[BB * NK];
__device__ float g_mixed[BB * C_OUT * C_IN * 9];

// bf16 split tensors: x transposed to [b][y][x][ci], w to [b][tap][co][ci]
__device__ __nv_bfloat16 g_xh[(size_t)BB * HH * WW * C_IN];
__device__ __nv_bfloat16 g_xl[(size_t)BB * HH * WW * C_IN];
__device__ __nv_bfloat16 g_wh[(size_t)BB * 9 * C_OUT * C_IN];
__device__ __nv_bfloat16 g_wl[(size_t)BB * 9 * C_OUT * C_IN];

// ---------------- portable tensor-core helpers (sm_80+ PTX) ----------------
__device__ __forceinline__ void ldm_x4(uint32_t& r0, uint32_t& r1, uint32_t& r2,
                                       uint32_t& r3, uint32_t addr) {
    asm volatile("ldmatrix.sync.aligned.m8n8.x4.shared.b16 {%0,%1,%2,%3}, [%4];"
                 : "=r"(r0), "=r"(r1), "=r"(r2), "=r"(r3) : "r"(addr));
}
__device__ __forceinline__ void ldm_x2(uint32_t& r0, uint32_t& r1, uint32_t addr) {
    asm volatile("ldmatrix.sync.aligned.m8n8.x2.shared.b16 {%0,%1}, [%2];"
                 : "=r"(r0), "=r"(r1) : "r"(addr));
}
__device__ __forceinline__ void mma_bf16(float* c, const uint32_t* a,
                                         const uint32_t* bfr) {
    asm volatile(
        "mma.sync.aligned.m16n8k16.row.col.f32.bf16.bf16.f32 "
        "{%0,%1,%2,%3}, {%4,%5,%6,%7}, {%8,%9}, {%0,%1,%2,%3};"
        : "+f"(c[0]), "+f"(c[1]), "+f"(c[2]), "+f"(c[3])
        : "r"(a[0]), "r"(a[1]), "r"(a[2]), "r"(a[3]), "r"(bfr[0]), "r"(bfr[1]));
}

// ---------------- Kernel 1: global average pool ----------------
__global__ void pool_kernel(const float* __restrict__ x) {
    int idx = blockIdx.x;  // b*C_IN + ci
    const float4* p = reinterpret_cast<const float4*>(x + (size_t)idx * (HH * WW));
    float s = 0.f;
    for (int i = threadIdx.x; i < (HH * WW) / 4; i += blockDim.x) {
        float4 v = p[i];
        s += v.x + v.y + v.z + v.w;
    }
    __shared__ float red[256];
    red[threadIdx.x] = s;
    __syncthreads();
    for (int off = 128; off > 0; off >>= 1) {
        if (threadIdx.x < off) red[threadIdx.x] += red[threadIdx.x + off];
        __syncthreads();
    }
    if (threadIdx.x == 0) g_pooled[idx] = red[0] * (1.0f / (HH * WW));
}

// ---------------- Kernel 2: logits + softmax ----------------
__global__ void attn_kernel(const float* __restrict__ attn_w,
                            const float* __restrict__ attn_b) {
    __shared__ float lg[BB * NK];
    int t = threadIdx.x;
    if (t < BB * NK) {
        int b = t / NK, n = t % NK;
        float s = attn_b[n];
        #pragma unroll 8
        for (int c = 0; c < C_IN; c++) s += g_pooled[b * C_IN + c] * attn_w[n * C_IN + c];
        lg[t] = s;
    }
    __syncthreads();
    if (t < BB) {
        float m = -1e30f;
        for (int n = 0; n < NK; n++) m = fmaxf(m, lg[t * NK + n]);
        float e[NK];
        float sum = 0.f;
        for (int n = 0; n < NK; n++) { e[n] = expf(lg[t * NK + n] - m); sum += e[n]; }
        float inv = 1.0f / sum;
        for (int n = 0; n < NK; n++) g_attn[t * NK + n] = e[n] * inv;
    }
}

// ---------------- Kernel 3: mix kernel bank ----------------
__global__ void mix_kernel(const float* __restrict__ bank) {
    const int R = C_OUT * C_IN * 9;
    int i = blockIdx.x * blockDim.x + threadIdx.x;
    if (i >= BB * R) return;
    int b = i / R, r = i - b * R;
    float s = 0.f;
    #pragma unroll
    for (int n = 0; n < NK; n++) s += g_attn[b * NK + n] * bank[(size_t)n * R + r];
    g_mixed[i] = s;
}

// ------- Kernel 3b: split mixed weights to bf16 hi/lo, [b][tap][co][ci] -------
__global__ void split_w_kernel() {
    int i = blockIdx.x * blockDim.x + threadIdx.x;   // over b*co*ci
    if (i >= BB * C_OUT * C_IN) return;
    int ci = i & 63;
    int co = (i >> 6) & 127;
    int b = i >> 13;
    const float* src = g_mixed + ((size_t)i) * 9;
    #pragma unroll
    for (int tap = 0; tap < 9; tap++) {
        float v = src[tap];
        __nv_bfloat16 h = __float2bfloat16(v);
        __nv_bfloat16 l = __float2bfloat16(v - __bfloat162float(h));
        size_t o = ((((size_t)b * 9 + tap) * C_OUT + co) * C_IN) + ci;
        g_wh[o] = h;
        g_wl[o] = l;
    }
}

// ------- Kernel 3c: split + transpose x -> [b][y][x][ci] bf16 hi/lo -------
__global__ void __launch_bounds__(256) split_x_kernel(const float* __restrict__ x) {
    int y = blockIdx.x;
    int b = blockIdx.y;
    int xc = threadIdx.x;   // 0..255
    const float* xp = x + ((size_t)b * C_IN) * (HH * WW) + y * WW + xc;
    uint32_t hi2[C_IN / 2], lo2[C_IN / 2];
    #pragma unroll
    for (int c = 0; c < C_IN; c += 2) {
        float v0 = xp[(size_t)c * (HH * WW)];
        float v1 = xp[(size_t)(c + 1) * (HH * WW)];
        __nv_bfloat16 h0 = __float2bfloat16(v0);
        __nv_bfloat16 h1 = __float2bfloat16(v1);
        __nv_bfloat16 l0 = __float2bfloat16(v0 - __bfloat162float(h0));
        __nv_bfloat16 l1 = __float2bfloat16(v1 - __bfloat162float(h1));
        hi2[c / 2] = (uint32_t)__bfloat16_as_ushort(h0) |
                     ((uint32_t)__bfloat16_as_ushort(h1) << 16);
        lo2[c / 2] = (uint32_t)__bfloat16_as_ushort(l0) |
                     ((uint32_t)__bfloat16_as_ushort(l1) << 16);
    }
    size_t o = (((size_t)b * HH + y) * WW + xc) * C_IN;
    uint4* dh = reinterpret_cast<uint4*>(g_xh + o);
    uint4* dl = reinterpret_cast<uint4*>(g_xl + o);
    #pragma unroll
    for (int j = 0; j < C_IN / 8; j++) {
        dh[j] = make_uint4(hi2[j * 4], hi2[j * 4 + 1], hi2[j * 4 + 2], hi2[j * 4 + 3]);
        dl[j] = make_uint4(lo2[j * 4], lo2[j * 4 + 1], lo2[j * 4 + 2], lo2[j * 4 + 3]);
    }
}

// ---------------- Kernel 4: HMMA implicit-GEMM conv ----------------
// CTA: 256 thr = 8 warps (2 M x 4 N). Tile M=128 pixels (x-segment of one y row),
// N=128 c_out, K = 9 taps x 64 ci, 3-term bf16 split, fp32 HMMA accumulators.
// A staged ONCE (3 y-blocks x 132 x-halo rows, zero-filled OOB); W staged per tap.
__global__ void __launch_bounds__(256, 1) conv_tc_kernel(float* __restrict__ out) {
    extern __shared__ __nv_bfloat16 smem[];
    __nv_bfloat16* sA = smem;                       // [2][AROWS][APITCH]
    __nv_bfloat16* sW = smem + 2 * AROWS * APITCH;  // [2][WROWS][APITCH]

    const int tid = threadIdx.x;
    const int lane = tid & 31;
    const int wid = tid >> 5;
    const int wm = wid >> 2;          // 0..1  (M)
    const int wn = wid & 3;           // 0..3  (N)
    const int x0 = blockIdx.x * 128;
    const int y = blockIdx.y;
    const int b = blockIdx.z;

    uint32_t sA_u32 = (uint32_t)__cvta_generic_to_shared(sA);
    uint32_t sW_u32 = (uint32_t)__cvta_generic_to_shared(sW);

    // ---- stage A: rows r = blk*132 + xi ; (y-1+blk, x0-1+xi), both halves ----
    const uint4 z4 = make_uint4(0, 0, 0, 0);
    for (int i = tid; i < 2 * AROWS; i += 256) {
        int half = i >= AROWS ? 1 : 0;
        int r = i - half * AROWS;
        int blk = r / 132, xi = r - blk * 132;
        int yy = y - 1 + blk;
        int xx = x0 + xi - 1;
        bool v = (yy >= 0) && (yy < HH) && (xi < 130) && (xx >= 0) && (xx < WW);
        const __nv_bfloat16* gsrc = (half ? g_xl : g_xh) +
            (((size_t)b * HH + (v ? yy : 0)) * WW + (v ? xx : 0)) * C_IN;
        const uint4* src = reinterpret_cast<const uint4*>(gsrc);
        uint4* dst = reinterpret_cast<uint4*>(sA + (size_t)i * APITCH);
        #pragma unroll
        for (int j = 0; j < 8; j++) dst[j] = v ? src[j] : z4;
    }

    float acc[4][4][4];
    #pragma unroll
    for (int mt = 0; mt < 4; mt++)
        #pragma unroll
        for (int nt = 0; nt < 4; nt++)
            #pragma unroll
            for (int q = 0; q < 4; q++) acc[mt][nt][q] = 0.f;

    // lane-derived ldmatrix address components
    const int a_row_l = lane & 15;
    const int a_koff_l = (lane >> 4) * 16;   // bytes
    const int b_row_l = lane & 7;
    const int b_koff_l = ((lane >> 3) & 1) * 16;  // bytes (x2 uses lanes 0-15)

    __syncthreads();

    for (int tap = 0; tap < 9; tap++) {
        // ---- stage W for this tap (both halves), one row per thread ----
        {
            int half = tid >> 7;
            int co = tid & 127;
            const __nv_bfloat16* gsrc = (half ? g_wl : g_wh) +
                ((size_t)(b * 9 + tap) * C_OUT + co) * C_IN;
            const uint4* src = reinterpret_cast<const uint4*>(gsrc);
            uint4* dst = reinterpret_cast<uint4*>(sW + (size_t)tid * APITCH);
            #pragma unroll
            for (int j = 0; j < 8; j++) dst[j] = src[j];
        }
        __syncthreads();

        const int dy = tap / 3 - 1, dx = tap % 3 - 1;
        const int rbase = (dy + 1) * 132 + dx + 1 + 64 * wm;

        #pragma unroll
        for (int kc = 0; kc < 4; kc++) {
            uint32_t ah[4][4], al[4][4];
            #pragma unroll
            for (int mt = 0; mt < 4; mt++) {
                uint32_t rowoff = (uint32_t)(rbase + 16 * mt + a_row_l) * 144 +
                                  kc * 32 + a_koff_l;
                ldm_x4(ah[mt][0], ah[mt][1], ah[mt][2], ah[mt][3], sA_u32 + rowoff);
                ldm_x4(al[mt][0], al[mt][1], al[mt][2], al[mt][3],
                       sA_u32 + AROWS * 144 + rowoff);
            }
            #pragma unroll
            for (int nt = 0; nt < 4; nt++) {
                uint32_t browoff = (uint32_t)(32 * wn + 8 * nt + b_row_l) * 144 +
                                   kc * 32 + b_koff_l;
                uint32_t bh[2], bl[2];
                ldm_x2(bh[0], bh[1], sW_u32 + browoff);
                ldm_x2(bl[0], bl[1], sW_u32 + WROWS * 144 + browoff);
                #pragma unroll
                for (int mt = 0; mt < 4; mt++) mma_bf16(acc[mt][nt], ah[mt], bh);
                #pragma unroll
                for (int mt = 0; mt < 4; mt++) mma_bf16(acc[mt][nt], ah[mt], bl);
                #pragma unroll
                for (int mt = 0; mt < 4; mt++) mma_bf16(acc[mt][nt], al[mt], bh);
            }
        }
        __syncthreads();   // before overwriting sW next tap
    }

    // ---- epilogue: c-frag m16n8 layout -> out[b][co][y][px] ----
    const int gid = lane >> 2, qid = lane & 3;
    #pragma unroll
    for (int mt = 0; mt < 4; mt++) {
        int px0 = x0 + 64 * wm + 16 * mt + gid;
        #pragma unroll
        for (int nt = 0; nt < 4; nt++) {
            int co0 = 32 * wn + 8 * nt + 2 * qid;
            float* c = acc[mt][nt];
            size_t o00 = (((size_t)b * C_OUT + co0) * HH + y) * WW + px0;
            size_t o01 = o00 + (size_t)HH * WW;          // co0+1
            out[o00] = c[0];
            out[o01] = c[1];
            out[o00 + 8] = c[2];                          // px0+8
            out[o01 + 8] = c[3];
        }
    }
}

extern "C" void kernel_launch(void* const* d_in, const int* in_sizes, int n_in,
                              void* d_out, int out_size) {
    const float* x    = (const float*)d_in[0];
    const float* bank = (const float*)d_in[1];
    const float* aw   = (const float*)d_in[2];
    const float* ab   = (const float*)d_in[3];
    float* out = (float*)d_out;

    pool_kernel<<<BB * C_IN, 256>>>(x);
    attn_kernel<<<1, 64>>>(aw, ab);
    mix_kernel<<<(BB * C_OUT * C_IN * 9 + 255) / 256, 256>>>(bank);
    split_w_kernel<<<(BB * C_OUT * C_IN + 255) / 256, 256>>>();
    split_x_kernel<<<dim3(HH, BB), 256>>>(x);

    const int smem_bytes = (2 * AROWS + 2 * WROWS) * APITCH * 2;  // 150,912 B
    cudaFuncSetAttribute(conv_tc_kernel,
                         cudaFuncAttributeMaxDynamicSharedMemorySize, smem_bytes);
    dim3 g(WW / 128, HH, BB);
    conv_tc_kernel<<<g, 256, smem_bytes>>>(out);
}

// round 10
// speedup vs baseline: 1.8229x; 1.0491x over previous
#include <cuda_runtime.h>
#include <cuda_bf16.h>
#include <cstdint>

#define BB 8
#define C_IN 64
#define C_OUT 128
#define HH 256
#define WW 256
#define NK 8

#define APITCH 72            // bf16 elems per smem row (144B, conflict-free ldmatrix)
#define AROWS 264            // 4 y-blocks x 66 x-halo entries
#define WROWS 128

__device__ float g_pooled[BB * C_IN];
__device__ float g_attn[BB * NK];
__device__ float g_mixed[BB * C_OUT * C_IN * 9];

// bf16 split tensors: x transposed to [b][y][x][ci], w to [b][tap][co][ci]
__device__ __nv_bfloat16 g_xh[(size_t)BB * HH * WW * C_IN];
__device__ __nv_bfloat16 g_xl[(size_t)BB * HH * WW * C_IN];
__device__ __nv_bfloat16 g_wh[(size_t)BB * 9 * C_OUT * C_IN];
__device__ __nv_bfloat16 g_wl[(size_t)BB * 9 * C_OUT * C_IN];

// ---------------- portable tensor-core helpers (sm_80+ PTX) ----------------
__device__ __forceinline__ void ldm_x4(uint32_t& r0, uint32_t& r1, uint32_t& r2,
                                       uint32_t& r3, uint32_t addr) {
    asm volatile("ldmatrix.sync.aligned.m8n8.x4.shared.b16 {%0,%1,%2,%3}, [%4];"
                 : "=r"(r0), "=r"(r1), "=r"(r2), "=r"(r3) : "r"(addr));
}
__device__ __forceinline__ void mma_bf16(float* c, const uint32_t* a,
                                         const uint32_t* bfr) {
    asm volatile(
        "mma.sync.aligned.m16n8k16.row.col.f32.bf16.bf16.f32 "
        "{%0,%1,%2,%3}, {%4,%5,%6,%7}, {%8,%9}, {%0,%1,%2,%3};"
        : "+f"(c[0]), "+f"(c[1]), "+f"(c[2]), "+f"(c[3])
        : "r"(a[0]), "r"(a[1]), "r"(a[2]), "r"(a[3]), "r"(bfr[0]), "r"(bfr[1]));
}

// ---------------- Kernel 1: global average pool ----------------
__global__ void pool_kernel(const float* __restrict__ x) {
    int idx = blockIdx.x;  // b*C_IN + ci
    const float4* p = reinterpret_cast<const float4*>(x + (size_t)idx * (HH * WW));
    float s = 0.f;
    for (int i = threadIdx.x; i < (HH * WW) / 4; i += blockDim.x) {
        float4 v = p[i];
        s += v.x + v.y + v.z + v.w;
    }
    __shared__ float red[256];
    red[threadIdx.x] = s;
    __syncthreads();
    for (int off = 128; off > 0; off >>= 1) {
        if (threadIdx.x < off) red[threadIdx.x] += red[threadIdx.x + off];
        __syncthreads();
    }
    if (threadIdx.x == 0) g_pooled[idx] = red[0] * (1.0f / (HH * WW));
}

// ---------------- Kernel 2: logits + softmax ----------------
__global__ void attn_kernel(const float* __restrict__ attn_w,
                            const float* __restrict__ attn_b) {
    __shared__ float lg[BB * NK];
    int t = threadIdx.x;
    if (t < BB * NK) {
        int b = t / NK, n = t % NK;
        float s = attn_b[n];
        #pragma unroll 8
        for (int c = 0; c < C_IN; c++) s += g_pooled[b * C_IN + c] * attn_w[n * C_IN + c];
        lg[t] = s;
    }
    __syncthreads();
    if (t < BB) {
        float m = -1e30f;
        for (int n = 0; n < NK; n++) m = fmaxf(m, lg[t * NK + n]);
        float e[NK];
        float sum = 0.f;
        for (int n = 0; n < NK; n++) { e[n] = expf(lg[t * NK + n] - m); sum += e[n]; }
        float inv = 1.0f / sum;
        for (int n = 0; n < NK; n++) g_attn[t * NK + n] = e[n] * inv;
    }
}

// ---------------- Kernel 3: mix kernel bank ----------------
__global__ void mix_kernel(const float* __restrict__ bank) {
    const int R = C_OUT * C_IN * 9;
    int i = blockIdx.x * blockDim.x + threadIdx.x;
    if (i >= BB * R) return;
    int b = i / R, r = i - b * R;
    float s = 0.f;
    #pragma unroll
    for (int n = 0; n < NK; n++) s += g_attn[b * NK + n] * bank[(size_t)n * R + r];
    g_mixed[i] = s;
}

// ------- Kernel 3b: split mixed weights to bf16 hi/lo, [b][tap][co][ci] -------
__global__ void split_w_kernel() {
    int i = blockIdx.x * blockDim.x + threadIdx.x;   // over b*co*ci
    if (i >= BB * C_OUT * C_IN) return;
    int ci = i & 63;
    int co = (i >> 6) & 127;
    int b = i >> 13;
    const float* src = g_mixed + ((size_t)i) * 9;
    #pragma unroll
    for (int tap = 0; tap < 9; tap++) {
        float v = src[tap];
        __nv_bfloat16 h = __float2bfloat16(v);
        __nv_bfloat16 l = __float2bfloat16(v - __bfloat162float(h));
        size_t o = ((((size_t)b * 9 + tap) * C_OUT + co) * C_IN) + ci;
        g_wh[o] = h;
        g_wl[o] = l;
    }
}

// ------- Kernel 3c: split + transpose x -> [b][y][x][ci] bf16 hi/lo -------
__global__ void __launch_bounds__(256) split_x_kernel(const float* __restrict__ x) {
    int y = blockIdx.x;
    int b = blockIdx.y;
    int xc = threadIdx.x;   // 0..255
    const float* xp = x + ((size_t)b * C_IN) * (HH * WW) + y * WW + xc;
    uint32_t hi2[C_IN / 2], lo2[C_IN / 2];
    #pragma unroll
    for (int c = 0; c < C_IN; c += 2) {
        float v0 = xp[(size_t)c * (HH * WW)];
        float v1 = xp[(size_t)(c + 1) * (HH * WW)];
        __nv_bfloat16 h0 = __float2bfloat16(v0);
        __nv_bfloat16 h1 = __float2bfloat16(v1);
        __nv_bfloat16 l0 = __float2bfloat16(v0 - __bfloat162float(h0));
        __nv_bfloat16 l1 = __float2bfloat16(v1 - __bfloat162float(h1));
        hi2[c / 2] = (uint32_t)__bfloat16_as_ushort(h0) |
                     ((uint32_t)__bfloat16_as_ushort(h1) << 16);
        lo2[c / 2] = (uint32_t)__bfloat16_as_ushort(l0) |
                     ((uint32_t)__bfloat16_as_ushort(l1) << 16);
    }
    size_t o = (((size_t)b * HH + y) * WW + xc) * C_IN;
    uint4* dh = reinterpret_cast<uint4*>(g_xh + o);
    uint4* dl = reinterpret_cast<uint4*>(g_xl + o);
    #pragma unroll
    for (int j = 0; j < C_IN / 8; j++) {
        dh[j] = make_uint4(hi2[j * 4], hi2[j * 4 + 1], hi2[j * 4 + 2], hi2[j * 4 + 3]);
        dl[j] = make_uint4(lo2[j * 4], lo2[j * 4 + 1], lo2[j * 4 + 2], lo2[j * 4 + 3]);
    }
}

// ---------------- Kernel 4: HMMA implicit-GEMM conv ----------------
// CTA: 256 thr = 8 warps (2 M x 4 N). Tile M=128 pixels = 2 y-rows x 64 px,
// N=128 c_out, K = 9 taps x 64 ci, 3-term bf16 split, fp32 HMMA accumulators.
// A staged ONCE (4 y-blocks x 66 x-halo rows, zero-filled OOB); W staged per tap.
// smem = 112.9KB -> 2 CTAs/SM; cross-CTA overlap hides W staging syncs.
__global__ void __launch_bounds__(256, 2) conv_tc_kernel(float* __restrict__ out) {
    extern __shared__ __nv_bfloat16 smem[];
    __nv_bfloat16* sA = smem;                       // [2][AROWS][APITCH]
    __nv_bfloat16* sW = smem + 2 * AROWS * APITCH;  // [2][WROWS][APITCH]

    const int tid = threadIdx.x;
    const int lane = tid & 31;
    const int wid = tid >> 5;
    const int wm = wid >> 2;          // 0..1  (local y row)
    const int wn = wid & 3;           // 0..3  (N / c_out group)
    const int x0 = blockIdx.x * 64;
    const int y0 = blockIdx.y * 2;
    const int b = blockIdx.z;

    uint32_t sA_u32 = (uint32_t)__cvta_generic_to_shared(sA);
    uint32_t sW_u32 = (uint32_t)__cvta_generic_to_shared(sW);

    // ---- stage A: rows r = yblk*66 + xi ; (y0-1+yblk, x0-1+xi), both halves ----
    const uint4 z4 = make_uint4(0, 0, 0, 0);
    for (int i = tid; i < 2 * AROWS; i += 256) {
        int half = i >= AROWS ? 1 : 0;
        int r = i - half * AROWS;
        int yblk = r / 66, xi = r - yblk * 66;
        int yy = y0 - 1 + yblk;
        int xx = x0 + xi - 1;
        bool v = (yy >= 0) && (yy < HH) && (xx >= 0) && (xx < WW);
        const __nv_bfloat16* gsrc = (half ? g_xl : g_xh) +
            (((size_t)b * HH + (v ? yy : 0)) * WW + (v ? xx : 0)) * C_IN;
        const uint4* src = reinterpret_cast<const uint4*>(gsrc);
        uint4* dst = reinterpret_cast<uint4*>(sA + (size_t)i * APITCH);
        #pragma unroll
        for (int j = 0; j < 8; j++) dst[j] = v ? src[j] : z4;
    }

    float acc[4][4][4];
    #pragma unroll
    for (int mt = 0; mt < 4; mt++)
        #pragma unroll
        for (int nt = 0; nt < 4; nt++)
            #pragma unroll
            for (int q = 0; q < 4; q++) acc[mt][nt][q] = 0.f;

    // lane-derived ldmatrix address components (same pattern for A and B x4)
    const int row16_l = lane & 15;
    const int koff_l = (lane >> 4) * 16;   // bytes

    __syncthreads();

    for (int tap = 0; tap < 9; tap++) {
        // ---- stage W for this tap (both halves), one row per thread ----
        {
            int half = tid >> 7;
            int co = tid & 127;
            const __nv_bfloat16* gsrc = (half ? g_wl : g_wh) +
                ((size_t)(b * 9 + tap) * C_OUT + co) * C_IN;
            const uint4* src = reinterpret_cast<const uint4*>(gsrc);
            uint4* dst = reinterpret_cast<uint4*>(sW + (size_t)tid * APITCH);
            #pragma unroll
            for (int j = 0; j < 8; j++) dst[j] = src[j];
        }
        __syncthreads();

        const int dy = tap / 3 - 1, dx = tap % 3 - 1;
        const int arow0 = (wm + dy + 1) * 66 + (dx + 1);

        #pragma unroll
        for (int kc = 0; kc < 4; kc++) {
            const uint32_t kb = (uint32_t)(kc * 32 + koff_l);
            // A fragments: 4 m16 tiles x 2 halves
            uint32_t ah[4][4], al[4][4];
            #pragma unroll
            for (int mt = 0; mt < 4; mt++) {
                uint32_t rowoff = (uint32_t)(arow0 + 16 * mt + row16_l) * 144 + kb;
                ldm_x4(ah[mt][0], ah[mt][1], ah[mt][2], ah[mt][3], sA_u32 + rowoff);
                ldm_x4(al[mt][0], al[mt][1], al[mt][2], al[mt][3],
                       sA_u32 + AROWS * 144 + rowoff);
            }
            // B fragments: 2 n16 pair-tiles x 2 halves (x4 = two n8 frags each)
            #pragma unroll
            for (int ntp = 0; ntp < 2; ntp++) {
                uint32_t browoff = (uint32_t)(32 * wn + 16 * ntp + row16_l) * 144 + kb;
                uint32_t h0, h1, h2, h3, l0, l1, l2, l3;
                ldm_x4(h0, h1, h2, h3, sW_u32 + browoff);
                ldm_x4(l0, l1, l2, l3, sW_u32 + WROWS * 144 + browoff);
                uint32_t bh0[2] = {h0, h2}, bh1[2] = {h1, h3};
                uint32_t bl0[2] = {l0, l2}, bl1[2] = {l1, l3};
                int nt0 = 2 * ntp, nt1 = 2 * ntp + 1;
                #pragma unroll
                for (int mt = 0; mt < 4; mt++) {
                    mma_bf16(acc[mt][nt0], ah[mt], bh0);
                    mma_bf16(acc[mt][nt1], ah[mt], bh1);
                    mma_bf16(acc[mt][nt0], ah[mt], bl0);
                    mma_bf16(acc[mt][nt1], ah[mt], bl1);
                    mma_bf16(acc[mt][nt0], al[mt], bh0);
                    mma_bf16(acc[mt][nt1], al[mt], bh1);
                }
            }
        }
        __syncthreads();   // before overwriting sW next tap
    }

    // ---- epilogue: c-frag m16n8 layout -> out[b][co][y][px] ----
    const int gid = lane >> 2, qid = lane & 3;
    const int yo = y0 + wm;
    #pragma unroll
    for (int mt = 0; mt < 4; mt++) {
        int px0 = x0 + 16 * mt + gid;
        #pragma unroll
        for (int nt = 0; nt < 4; nt++) {
            int co0 = 32 * wn + 8 * nt + 2 * qid;
            float* c = acc[mt][nt];
            size_t o00 = (((size_t)b * C_OUT + co0) * HH + yo) * WW + px0;
            size_t o01 = o00 + (size_t)HH * WW;          // co0+1
            out[o00] = c[0];
            out[o01] = c[1];
            out[o00 + 8] = c[2];                          // px0+8
            out[o01 + 8] = c[3];
        }
    }
}

extern "C" void kernel_launch(void* const* d_in, const int* in_sizes, int n_in,
                              void* d_out, int out_size) {
    const float* x    = (const float*)d_in[0];
    const float* bank = (const float*)d_in[1];
    const float* aw   = (const float*)d_in[2];
    const float* ab   = (const float*)d_in[3];
    float* out = (float*)d_out;

    pool_kernel<<<BB * C_IN, 256>>>(x);
    attn_kernel<<<1, 64>>>(aw, ab);
    mix_kernel<<<(BB * C_OUT * C_IN * 9 + 255) / 256, 256>>>(bank);
    split_w_kernel<<<(BB * C_OUT * C_IN + 255) / 256, 256>>>();
    split_x_kernel<<<dim3(HH, BB), 256>>>(x);

    const int smem_bytes = (2 * AROWS + 2 * WROWS) * APITCH * 2;  // 112,896 B
    cudaFuncSetAttribute(conv_tc_kernel,
                         cudaFuncAttributeMaxDynamicSharedMemorySize, smem_bytes);
    dim3 g(WW / 64, HH / 2, BB);
    conv_tc_kernel<<<g, 256, smem_bytes>>>(out);
}

// round 11
// speedup vs baseline: 2.7478x; 1.5073x over previous
#include <cuda_runtime.h>
#include <cuda_fp16.h>
#include <cstdint>

#define BB 8
#define C_IN 64
#define C_OUT 128
#define HH 256
#define WW 256
#define NK 8

#define APITCH 72            // fp16 elems per smem row (144B, conflict-free ldmatrix)
#define AROWS 264            // 4 y-blocks x 66 x-halo entries
#define WROWS 128

__device__ float g_pooled[BB * C_IN];
__device__ float g_attn[BB * NK];
__device__ float g_mixed[BB * C_OUT * C_IN * 9];

// fp16 tensors: x (single) transposed to [b][y][x][ci]; w split hi/lo [b][tap][co][ci]
__device__ __half g_x16[(size_t)BB * HH * WW * C_IN];
__device__ __half g_wh[(size_t)BB * 9 * C_OUT * C_IN];
__device__ __half g_wl[(size_t)BB * 9 * C_OUT * C_IN];

// ---------------- portable tensor-core helpers (sm_80+ PTX) ----------------
__device__ __forceinline__ void ldm_x4(uint32_t& r0, uint32_t& r1, uint32_t& r2,
                                       uint32_t& r3, uint32_t addr) {
    asm volatile("ldmatrix.sync.aligned.m8n8.x4.shared.b16 {%0,%1,%2,%3}, [%4];"
                 : "=r"(r0), "=r"(r1), "=r"(r2), "=r"(r3) : "r"(addr));
}
__device__ __forceinline__ void mma_fp16(float* c, const uint32_t* a,
                                         const uint32_t* bfr) {
    asm volatile(
        "mma.sync.aligned.m16n8k16.row.col.f32.f16.f16.f32 "
        "{%0,%1,%2,%3}, {%4,%5,%6,%7}, {%8,%9}, {%0,%1,%2,%3};"
        : "+f"(c[0]), "+f"(c[1]), "+f"(c[2]), "+f"(c[3])
        : "r"(a[0]), "r"(a[1]), "r"(a[2]), "r"(a[3]), "r"(bfr[0]), "r"(bfr[1]));
}

// ---------------- Kernel 1: global average pool ----------------
__global__ void pool_kernel(const float* __restrict__ x) {
    int idx = blockIdx.x;  // b*C_IN + ci
    const float4* p = reinterpret_cast<const float4*>(x + (size_t)idx * (HH * WW));
    float s = 0.f;
    for (int i = threadIdx.x; i < (HH * WW) / 4; i += blockDim.x) {
        float4 v = p[i];
        s += v.x + v.y + v.z + v.w;
    }
    __shared__ float red[256];
    red[threadIdx.x] = s;
    __syncthreads();
    for (int off = 128; off > 0; off >>= 1) {
        if (threadIdx.x < off) red[threadIdx.x] += red[threadIdx.x + off];
        __syncthreads();
    }
    if (threadIdx.x == 0) g_pooled[idx] = red[0] * (1.0f / (HH * WW));
}

// ---------------- Kernel 2: logits + softmax ----------------
__global__ void attn_kernel(const float* __restrict__ attn_w,
                            const float* __restrict__ attn_b) {
    __shared__ float lg[BB * NK];
    int t = threadIdx.x;
    if (t < BB * NK) {
        int b = t / NK, n = t % NK;
        float s = attn_b[n];
        #pragma unroll 8
        for (int c = 0; c < C_IN; c++) s += g_pooled[b * C_IN + c] * attn_w[n * C_IN + c];
        lg[t] = s;
    }
    __syncthreads();
    if (t < BB) {
        float m = -1e30f;
        for (int n = 0; n < NK; n++) m = fmaxf(m, lg[t * NK + n]);
        float e[NK];
        float sum = 0.f;
        for (int n = 0; n < NK; n++) { e[n] = expf(lg[t * NK + n] - m); sum += e[n]; }
        float inv = 1.0f / sum;
        for (int n = 0; n < NK; n++) g_attn[t * NK + n] = e[n] * inv;
    }
}

// ---------------- Kernel 3: mix kernel bank ----------------
__global__ void mix_kernel(const float* __restrict__ bank) {
    const int R = C_OUT * C_IN * 9;
    int i = blockIdx.x * blockDim.x + threadIdx.x;
    if (i >= BB * R) return;
    int b = i / R, r = i - b * R;
    float s = 0.f;
    #pragma unroll
    for (int n = 0; n < NK; n++) s += g_attn[b * NK + n] * bank[(size_t)n * R + r];
    g_mixed[i] = s;
}

// ------- Kernel 3b: split mixed weights to fp16 hi/lo, [b][tap][co][ci] -------
__global__ void split_w_kernel() {
    int i = blockIdx.x * blockDim.x + threadIdx.x;   // over b*co*ci
    if (i >= BB * C_OUT * C_IN) return;
    int ci = i & 63;
    int co = (i >> 6) & 127;
    int b = i >> 13;
    const float* src = g_mixed + ((size_t)i) * 9;
    #pragma unroll
    for (int tap = 0; tap < 9; tap++) {
        float v = src[tap];
        __half h = __float2half(v);
        __half l = __float2half(v - __half2float(h));
        size_t o = ((((size_t)b * 9 + tap) * C_OUT + co) * C_IN) + ci;
        g_wh[o] = h;
        g_wl[o] = l;
    }
}

// ------- Kernel 3c: convert + transpose x -> [b][y][x][ci] fp16 -------
__global__ void __launch_bounds__(256) split_x_kernel(const float* __restrict__ x) {
    int y = blockIdx.x;
    int b = blockIdx.y;
    int xc = threadIdx.x;   // 0..255
    const float* xp = x + ((size_t)b * C_IN) * (HH * WW) + y * WW + xc;
    uint32_t h2[C_IN / 2];
    #pragma unroll
    for (int c = 0; c < C_IN; c += 2) {
        __half h0 = __float2half(xp[(size_t)c * (HH * WW)]);
        __half h1 = __float2half(xp[(size_t)(c + 1) * (HH * WW)]);
        h2[c / 2] = (uint32_t)__half_as_ushort(h0) |
                    ((uint32_t)__half_as_ushort(h1) << 16);
    }
    size_t o = (((size_t)b * HH + y) * WW + xc) * C_IN;
    uint4* dh = reinterpret_cast<uint4*>(g_x16 + o);
    #pragma unroll
    for (int j = 0; j < C_IN / 8; j++)
        dh[j] = make_uint4(h2[j * 4], h2[j * 4 + 1], h2[j * 4 + 2], h2[j * 4 + 3]);
}

// ---------------- Kernel 4: HMMA implicit-GEMM conv ----------------
// CTA: 256 thr = 8 warps (2 M x 4 N). Tile M=128 pixels = 2 y-rows x 64 px,
// N=128 c_out, K = 9 taps x 64 ci. fp16 asymmetric split: x single fp16,
// w = wh + wl (fp16 pair) -> 2 MMA terms, fp32 accumulators.
// A staged ONCE (4 y-blocks x 66 x-halo rows, zero-filled OOB); W staged per tap.
// smem = 73.1KB -> 2 CTAs/SM.
__global__ void __launch_bounds__(256, 2) conv_tc_kernel(float* __restrict__ out) {
    extern __shared__ __half smem[];
    __half* sA = smem;                          // [AROWS][APITCH]
    __half* sW = smem + AROWS * APITCH;         // [2][WROWS][APITCH]

    const int tid = threadIdx.x;
    const int lane = tid & 31;
    const int wid = tid >> 5;
    const int wm = wid >> 2;          // 0..1  (local y row)
    const int wn = wid & 3;           // 0..3  (N / c_out group)
    const int x0 = blockIdx.x * 64;
    const int y0 = blockIdx.y * 2;
    const int b = blockIdx.z;

    uint32_t sA_u32 = (uint32_t)__cvta_generic_to_shared(sA);
    uint32_t sW_u32 = (uint32_t)__cvta_generic_to_shared(sW);

    // ---- stage A: rows r = yblk*66 + xi ; (y0-1+yblk, x0-1+xi) ----
    const uint4 z4 = make_uint4(0, 0, 0, 0);
    for (int i = tid; i < AROWS; i += 256) {
        int yblk = i / 66, xi = i - yblk * 66;
        int yy = y0 - 1 + yblk;
        int xx = x0 + xi - 1;
        bool v = (yy >= 0) && (yy < HH) && (xx >= 0) && (xx < WW);
        const __half* gsrc = g_x16 +
            (((size_t)b * HH + (v ? yy : 0)) * WW + (v ? xx : 0)) * C_IN;
        const uint4* src = reinterpret_cast<const uint4*>(gsrc);
        uint4* dst = reinterpret_cast<uint4*>(sA + (size_t)i * APITCH);
        #pragma unroll
        for (int j = 0; j < 8; j++) dst[j] = v ? src[j] : z4;
    }

    float acc[4][4][4];
    #pragma unroll
    for (int mt = 0; mt < 4; mt++)
        #pragma unroll
        for (int nt = 0; nt < 4; nt++)
            #pragma unroll
            for (int q = 0; q < 4; q++) acc[mt][nt][q] = 0.f;

    // lane-derived ldmatrix address components (same pattern for A and B x4)
    const int row16_l = lane & 15;
    const int koff_l = (lane >> 4) * 16;   // bytes

    __syncthreads();

    for (int tap = 0; tap < 9; tap++) {
        // ---- stage W for this tap (both halves), one row per thread ----
        {
            int half = tid >> 7;
            int co = tid & 127;
            const __half* gsrc = (half ? g_wl : g_wh) +
                ((size_t)(b * 9 + tap) * C_OUT + co) * C_IN;
            const uint4* src = reinterpret_cast<const uint4*>(gsrc);
            uint4* dst = reinterpret_cast<uint4*>(sW + (size_t)tid * APITCH);
            #pragma unroll
            for (int j = 0; j < 8; j++) dst[j] = src[j];
        }
        __syncthreads();

        const int dy = tap / 3 - 1, dx = tap % 3 - 1;
        const int arow0 = (wm + dy + 1) * 66 + (dx + 1);

        #pragma unroll
        for (int kc = 0; kc < 4; kc++) {
            const uint32_t kb = (uint32_t)(kc * 32 + koff_l);
            // A fragments: 4 m16 tiles (single fp16 x)
            uint32_t ah[4][4];
            #pragma unroll
            for (int mt = 0; mt < 4; mt++) {
                uint32_t rowoff = (uint32_t)(arow0 + 16 * mt + row16_l) * 144 + kb;
                ldm_x4(ah[mt][0], ah[mt][1], ah[mt][2], ah[mt][3], sA_u32 + rowoff);
            }
            // B fragments: 2 n16 pair-tiles x 2 halves (x4 = two n8 frags each)
            #pragma unroll
            for (int ntp = 0; ntp < 2; ntp++) {
                uint32_t browoff = (uint32_t)(32 * wn + 16 * ntp + row16_l) * 144 + kb;
                uint32_t h0, h1, h2, h3, l0, l1, l2, l3;
                ldm_x4(h0, h1, h2, h3, sW_u32 + browoff);
                ldm_x4(l0, l1, l2, l3, sW_u32 + WROWS * 144 + browoff);
                uint32_t bh0[2] = {h0, h2}, bh1[2] = {h1, h3};
                uint32_t bl0[2] = {l0, l2}, bl1[2] = {l1, l3};
                int nt0 = 2 * ntp, nt1 = 2 * ntp + 1;
                #pragma unroll
                for (int mt = 0; mt < 4; mt++) {
                    mma_fp16(acc[mt][nt0], ah[mt], bh0);
                    mma_fp16(acc[mt][nt1], ah[mt], bh1);
                    mma_fp16(acc[mt][nt0], ah[mt], bl0);
                    mma_fp16(acc[mt][nt1], ah[mt], bl1);
                }
            }
        }
        __syncthreads();   // before overwriting sW next tap
    }

    // ---- epilogue: c-frag m16n8 layout -> out[b][co][y][px] ----
    const int gid = lane >> 2, qid = lane & 3;
    const int yo = y0 + wm;
    #pragma unroll
    for (int mt = 0; mt < 4; mt++) {
        int px0 = x0 + 16 * mt + gid;
        #pragma unroll
        for (int nt = 0; nt < 4; nt++) {
            int co0 = 32 * wn + 8 * nt + 2 * qid;
            float* c = acc[mt][nt];
            size_t o00 = (((size_t)b * C_OUT + co0) * HH + yo) * WW + px0;
            size_t o01 = o00 + (size_t)HH * WW;          // co0+1
            out[o00] = c[0];
            out[o01] = c[1];
            out[o00 + 8] = c[2];                          // px0+8
            out[o01 + 8] = c[3];
        }
    }
}

extern "C" void kernel_launch(void* const* d_in, const int* in_sizes, int n_in,
                              void* d_out, int out_size) {
    const float* x    = (const float*)d_in[0];
    const float* bank = (const float*)d_in[1];
    const float* aw   = (const float*)d_in[2];
    const float* ab   = (const float*)d_in[3];
    float* out = (float*)d_out;

    pool_kernel<<<BB * C_IN, 256>>>(x);
    attn_kernel<<<1, 64>>>(aw, ab);
    mix_kernel<<<(BB * C_OUT * C_IN * 9 + 255) / 256, 256>>>(bank);
    split_w_kernel<<<(BB * C_OUT * C_IN + 255) / 256, 256>>>();
    split_x_kernel<<<dim3(HH, BB), 256>>>(x);

    const int smem_bytes = (AROWS + 2 * WROWS) * APITCH * 2;  // 74,880 B
    cudaFuncSetAttribute(conv_tc_kernel,
                         cudaFuncAttributeMaxDynamicSharedMemorySize, smem_bytes);
    dim3 g(WW / 64, HH / 2, BB);
    conv_tc_kernel<<<g, 256, smem_bytes>>>(out);
}

// round 12
// speedup vs baseline: 3.1944x; 1.1625x over previous
#include <cuda_runtime.h>
#include <cuda_fp16.h>
#include <cstdint>

#define BB 8
#define C_IN 64
#define C_OUT 128
#define HH 256
#define WW 256
#define NK 8

#define APITCH 72            // fp16 elems per smem row (144B, conflict-free ldmatrix)
#define AROWS 264            // 4 y-blocks x 66 x-halo entries
#define WROWS 128

__device__ float g_pooled[BB * C_IN];
__device__ float g_attn[BB * NK];
__device__ float g_mixed[BB * C_OUT * C_IN * 9];

// fp16 tensors: x transposed to [b][y][x][ci]; w [b][tap][co][ci]
__device__ __half g_x16[(size_t)BB * HH * WW * C_IN];
__device__ __half g_w16[(size_t)BB * 9 * C_OUT * C_IN];

// ---------------- portable tensor-core helpers (sm_80+ PTX) ----------------
__device__ __forceinline__ void ldm_x4(uint32_t& r0, uint32_t& r1, uint32_t& r2,
                                       uint32_t& r3, uint32_t addr) {
    asm volatile("ldmatrix.sync.aligned.m8n8.x4.shared.b16 {%0,%1,%2,%3}, [%4];"
                 : "=r"(r0), "=r"(r1), "=r"(r2), "=r"(r3) : "r"(addr));
}
__device__ __forceinline__ void mma_fp16(float* c, const uint32_t* a,
                                         const uint32_t* bfr) {
    asm volatile(
        "mma.sync.aligned.m16n8k16.row.col.f32.f16.f16.f32 "
        "{%0,%1,%2,%3}, {%4,%5,%6,%7}, {%8,%9}, {%0,%1,%2,%3};"
        : "+f"(c[0]), "+f"(c[1]), "+f"(c[2]), "+f"(c[3])
        : "r"(a[0]), "r"(a[1]), "r"(a[2]), "r"(a[3]), "r"(bfr[0]), "r"(bfr[1]));
}

// ---------------- Kernel 1: global average pool ----------------
__global__ void pool_kernel(const float* __restrict__ x) {
    int idx = blockIdx.x;  // b*C_IN + ci
    const float4* p = reinterpret_cast<const float4*>(x + (size_t)idx * (HH * WW));
    float s = 0.f;
    for (int i = threadIdx.x; i < (HH * WW) / 4; i += blockDim.x) {
        float4 v = p[i];
        s += v.x + v.y + v.z + v.w;
    }
    __shared__ float red[256];
    red[threadIdx.x] = s;
    __syncthreads();
    for (int off = 128; off > 0; off >>= 1) {
        if (threadIdx.x < off) red[threadIdx.x] += red[threadIdx.x + off];
        __syncthreads();
    }
    if (threadIdx.x == 0) g_pooled[idx] = red[0] * (1.0f / (HH * WW));
}

// ---------------- Kernel 2: logits + softmax ----------------
__global__ void attn_kernel(const float* __restrict__ attn_w,
                            const float* __restrict__ attn_b) {
    __shared__ float lg[BB * NK];
    int t = threadIdx.x;
    if (t < BB * NK) {
        int b = t / NK, n = t % NK;
        float s = attn_b[n];
        #pragma unroll 8
        for (int c = 0; c < C_IN; c++) s += g_pooled[b * C_IN + c] * attn_w[n * C_IN + c];
        lg[t] = s;
    }
    __syncthreads();
    if (t < BB) {
        float m = -1e30f;
        for (int n = 0; n < NK; n++) m = fmaxf(m, lg[t * NK + n]);
        float e[NK];
        float sum = 0.f;
        for (int n = 0; n < NK; n++) { e[n] = expf(lg[t * NK + n] - m); sum += e[n]; }
        float inv = 1.0f / sum;
        for (int n = 0; n < NK; n++) g_attn[t * NK + n] = e[n] * inv;
    }
}

// ---------------- Kernel 3: mix kernel bank ----------------
__global__ void mix_kernel(const float* __restrict__ bank) {
    const int R = C_OUT * C_IN * 9;
    int i = blockIdx.x * blockDim.x + threadIdx.x;
    if (i >= BB * R) return;
    int b = i / R, r = i - b * R;
    float s = 0.f;
    #pragma unroll
    for (int n = 0; n < NK; n++) s += g_attn[b * NK + n] * bank[(size_t)n * R + r];
    g_mixed[i] = s;
}

// ------- Kernel 3b: mixed weights -> fp16, [b][tap][co][ci] -------
__global__ void split_w_kernel() {
    int i = blockIdx.x * blockDim.x + threadIdx.x;   // over b*co*ci
    if (i >= BB * C_OUT * C_IN) return;
    int ci = i & 63;
    int co = (i >> 6) & 127;
    int b = i >> 13;
    const float* src = g_mixed + ((size_t)i) * 9;
    #pragma unroll
    for (int tap = 0; tap < 9; tap++) {
        size_t o = ((((size_t)b * 9 + tap) * C_OUT + co) * C_IN) + ci;
        g_w16[o] = __float2half(src[tap]);
    }
}

// ------- Kernel 3c: convert + transpose x -> [b][y][x][ci] fp16 -------
__global__ void __launch_bounds__(256) split_x_kernel(const float* __restrict__ x) {
    int y = blockIdx.x;
    int b = blockIdx.y;
    int xc = threadIdx.x;   // 0..255
    const float* xp = x + ((size_t)b * C_IN) * (HH * WW) + y * WW + xc;
    uint32_t h2[C_IN / 2];
    #pragma unroll
    for (int c = 0; c < C_IN; c += 2) {
        __half h0 = __float2half(xp[(size_t)c * (HH * WW)]);
        __half h1 = __float2half(xp[(size_t)(c + 1) * (HH * WW)]);
        h2[c / 2] = (uint32_t)__half_as_ushort(h0) |
                    ((uint32_t)__half_as_ushort(h1) << 16);
    }
    size_t o = (((size_t)b * HH + y) * WW + xc) * C_IN;
    uint4* dh = reinterpret_cast<uint4*>(g_x16 + o);
    #pragma unroll
    for (int j = 0; j < C_IN / 8; j++)
        dh[j] = make_uint4(h2[j * 4], h2[j * 4 + 1], h2[j * 4 + 2], h2[j * 4 + 3]);
}

// ---------------- Kernel 4: HMMA implicit-GEMM conv (pure fp16) ----------------
// CTA: 256 thr = 8 warps (2 M x 4 N). Tile M=128 pixels = 2 y-rows x 64 px,
// N=128 c_out, K = 9 taps x 64 ci, single fp16 term, fp32 accumulators.
// A staged ONCE (4 y-blocks x 66 x-halo rows, zero-filled OOB); W staged per tap.
// smem = 56.4KB -> 3 CTAs/SM; cross-CTA overlap hides W staging syncs.
__global__ void __launch_bounds__(256, 3) conv_tc_kernel(float* __restrict__ out) {
    extern __shared__ __half smem[];
    __half* sA = smem;                          // [AROWS][APITCH]
    __half* sW = smem + AROWS * APITCH;         // [WROWS][APITCH]

    const int tid = threadIdx.x;
    const int lane = tid & 31;
    const int wid = tid >> 5;
    const int wm = wid >> 2;          // 0..1  (local y row)
    const int wn = wid & 3;           // 0..3  (N / c_out group)
    const int x0 = blockIdx.x * 64;
    const int y0 = blockIdx.y * 2;
    const int b = blockIdx.z;

    uint32_t sA_u32 = (uint32_t)__cvta_generic_to_shared(sA);
    uint32_t sW_u32 = (uint32_t)__cvta_generic_to_shared(sW);

    // ---- stage A: rows r = yblk*66 + xi ; (y0-1+yblk, x0-1+xi) ----
    const uint4 z4 = make_uint4(0, 0, 0, 0);
    for (int i = tid; i < AROWS; i += 256) {
        int yblk = i / 66, xi = i - yblk * 66;
        int yy = y0 - 1 + yblk;
        int xx = x0 + xi - 1;
        bool v = (yy >= 0) && (yy < HH) && (xx >= 0) && (xx < WW);
        const __half* gsrc = g_x16 +
            (((size_t)b * HH + (v ? yy : 0)) * WW + (v ? xx : 0)) * C_IN;
        const uint4* src = reinterpret_cast<const uint4*>(gsrc);
        uint4* dst = reinterpret_cast<uint4*>(sA + (size_t)i * APITCH);
        #pragma unroll
        for (int j = 0; j < 8; j++) dst[j] = v ? src[j] : z4;
    }

    float acc[4][4][4];
    #pragma unroll
    for (int mt = 0; mt < 4; mt++)
        #pragma unroll
        for (int nt = 0; nt < 4; nt++)
            #pragma unroll
            for (int q = 0; q < 4; q++) acc[mt][nt][q] = 0.f;

    const int row16_l = lane & 15;
    const int koff_l = (lane >> 4) * 16;   // bytes

    __syncthreads();

    for (int tap = 0; tap < 9; tap++) {
        // ---- stage W for this tap: rows co = tid (128 threads), 2 rows each ----
        if (tid < 128) {
            const __half* gsrc = g_w16 + ((size_t)(b * 9 + tap) * C_OUT + tid) * C_IN;
            const uint4* src = reinterpret_cast<const uint4*>(gsrc);
            uint4* dst = reinterpret_cast<uint4*>(sW + (size_t)tid * APITCH);
            #pragma unroll
            for (int j = 0; j < 4; j++) dst[j] = src[j];
        } else {
            int co = tid - 128;
            const __half* gsrc = g_w16 + ((size_t)(b * 9 + tap) * C_OUT + co) * C_IN;
            const uint4* src = reinterpret_cast<const uint4*>(gsrc);
            uint4* dst = reinterpret_cast<uint4*>(sW + (size_t)co * APITCH);
            #pragma unroll
            for (int j = 4; j < 8; j++) dst[j] = src[j];
        }
        __syncthreads();

        const int dy = tap / 3 - 1, dx = tap % 3 - 1;
        const int arow0 = (wm + dy + 1) * 66 + (dx + 1);

        #pragma unroll
        for (int kc = 0; kc < 4; kc++) {
            const uint32_t kb = (uint32_t)(kc * 32 + koff_l);
            // A fragments: 4 m16 tiles
            uint32_t ah[4][4];
            #pragma unroll
            for (int mt = 0; mt < 4; mt++) {
                uint32_t rowoff = (uint32_t)(arow0 + 16 * mt + row16_l) * 144 + kb;
                ldm_x4(ah[mt][0], ah[mt][1], ah[mt][2], ah[mt][3], sA_u32 + rowoff);
            }
            // B fragments: 2 n16 pair-tiles (x4 = two n8 frags each)
            #pragma unroll
            for (int ntp = 0; ntp < 2; ntp++) {
                uint32_t browoff = (uint32_t)(32 * wn + 16 * ntp + row16_l) * 144 + kb;
                uint32_t h0, h1, h2, h3;
                ldm_x4(h0, h1, h2, h3, sW_u32 + browoff);
                uint32_t bh0[2] = {h0, h2}, bh1[2] = {h1, h3};
                int nt0 = 2 * ntp, nt1 = 2 * ntp + 1;
                #pragma unroll
                for (int mt = 0; mt < 4; mt++) {
                    mma_fp16(acc[mt][nt0], ah[mt], bh0);
                    mma_fp16(acc[mt][nt1], ah[mt], bh1);
                }
            }
        }
        __syncthreads();   // before overwriting sW next tap
    }

    // ---- epilogue: c-frag m16n8 layout -> out[b][co][y][px] ----
    const int gid = lane >> 2, qid = lane & 3;
    const int yo = y0 + wm;
    #pragma unroll
    for (int mt = 0; mt < 4; mt++) {
        int px0 = x0 + 16 * mt + gid;
        #pragma unroll
        for (int nt = 0; nt < 4; nt++) {
            int co0 = 32 * wn + 8 * nt + 2 * qid;
            float* c = acc[mt][nt];
            size_t o00 = (((size_t)b * C_OUT + co0) * HH + yo) * WW + px0;
            size_t o01 = o00 + (size_t)HH * WW;          // co0+1
            out[o00] = c[0];
            out[o01] = c[1];
            out[o00 + 8] = c[2];                          // px0+8
            out[o01 + 8] = c[3];
        }
    }
}

extern "C" void kernel_launch(void* const* d_in, const int* in_sizes, int n_in,
                              void* d_out, int out_size) {
    const float* x    = (const float*)d_in[0];
    const float* bank = (const float*)d_in[1];
    const float* aw   = (const float*)d_in[2];
    const float* ab   = (const float*)d_in[3];
    float* out = (float*)d_out;

    pool_kernel<<<BB * C_IN, 256>>>(x);
    attn_kernel<<<1, 64>>>(aw, ab);
    mix_kernel<<<(BB * C_OUT * C_IN * 9 + 255) / 256, 256>>>(bank);
    split_w_kernel<<<(BB * C_OUT * C_IN + 255) / 256, 256>>>();
    split_x_kernel<<<dim3(HH, BB), 256>>>(x);

    const int smem_bytes = (AROWS + WROWS) * APITCH * 2;  // 56,448 B
    cudaFuncSetAttribute(conv_tc_kernel,
                         cudaFuncAttributeMaxDynamicSharedMemorySize, smem_bytes);
    dim3 g(WW / 64, HH / 2, BB);
    conv_tc_kernel<<<g, 256, smem_bytes>>>(out);
}

// round 13
// speedup vs baseline: 3.9416x; 1.2339x over previous
#include <cuda_runtime.h>
#include <cuda_fp16.h>
#include <cstdint>

#define BB 8
#define C_IN 64
#define C_OUT 128
#define HH 256
#define WW 256
#define NK 8

#define APITCH 72            // fp16 elems per smem row (144B, conflict-free ldmatrix)
#define AROWS 264            // 4 y-blocks x 66 x-halo entries
#define WROWS 128

__device__ float g_pooled[BB * C_IN];
__device__ float g_attn[BB * NK];
__device__ float g_mixed[BB * C_OUT * C_IN * 9];

// fp16 tensors: x transposed to [b][y][x][ci]; w [b][tap][co][ci]
__device__ __half g_x16[(size_t)BB * HH * WW * C_IN];
__device__ __half g_w16[(size_t)BB * 9 * C_OUT * C_IN];

// ---------------- portable tensor-core helpers (sm_80+ PTX) ----------------
__device__ __forceinline__ void ldm_x4(uint32_t& r0, uint32_t& r1, uint32_t& r2,
                                       uint32_t& r3, uint32_t addr) {
    asm volatile("ldmatrix.sync.aligned.m8n8.x4.shared.b16 {%0,%1,%2,%3}, [%4];"
                 : "=r"(r0), "=r"(r1), "=r"(r2), "=r"(r3) : "r"(addr));
}
__device__ __forceinline__ void mma_fp16(float* c, const uint32_t* a,
                                         const uint32_t* bfr) {
    asm volatile(
        "mma.sync.aligned.m16n8k16.row.col.f32.f16.f16.f32 "
        "{%0,%1,%2,%3}, {%4,%5,%6,%7}, {%8,%9}, {%0,%1,%2,%3};"
        : "+f"(c[0]), "+f"(c[1]), "+f"(c[2]), "+f"(c[3])
        : "r"(a[0]), "r"(a[1]), "r"(a[2]), "r"(a[3]), "r"(bfr[0]), "r"(bfr[1]));
}
__device__ __forceinline__ void cpasync16(uint32_t saddr, const void* g) {
    asm volatile("cp.async.cg.shared.global [%0], [%1], 16;"
                 :: "r"(saddr), "l"(g));
}
__device__ __forceinline__ void cp_commit() {
    asm volatile("cp.async.commit_group;");
}
__device__ __forceinline__ void cp_wait1() {
    asm volatile("cp.async.wait_group 1;");
}

// ---------------- Kernel 1: global average pool ----------------
__global__ void pool_kernel(const float* __restrict__ x) {
    int idx = blockIdx.x;  // b*C_IN + ci
    const float4* p = reinterpret_cast<const float4*>(x + (size_t)idx * (HH * WW));
    float s = 0.f;
    for (int i = threadIdx.x; i < (HH * WW) / 4; i += blockDim.x) {
        float4 v = p[i];
        s += v.x + v.y + v.z + v.w;
    }
    __shared__ float red[256];
    red[threadIdx.x] = s;
    __syncthreads();
    for (int off = 128; off > 0; off >>= 1) {
        if (threadIdx.x < off) red[threadIdx.x] += red[threadIdx.x + off];
        __syncthreads();
    }
    if (threadIdx.x == 0) g_pooled[idx] = red[0] * (1.0f / (HH * WW));
}

// ---------------- Kernel 2: logits + softmax ----------------
__global__ void attn_kernel(const float* __restrict__ attn_w,
                            const float* __restrict__ attn_b) {
    __shared__ float lg[BB * NK];
    int t = threadIdx.x;
    if (t < BB * NK) {
        int b = t / NK, n = t % NK;
        float s = attn_b[n];
        #pragma unroll 8
        for (int c = 0; c < C_IN; c++) s += g_pooled[b * C_IN + c] * attn_w[n * C_IN + c];
        lg[t] = s;
    }
    __syncthreads();
    if (t < BB) {
        float m = -1e30f;
        for (int n = 0; n < NK; n++) m = fmaxf(m, lg[t * NK + n]);
        float e[NK];
        float sum = 0.f;
        for (int n = 0; n < NK; n++) { e[n] = expf(lg[t * NK + n] - m); sum += e[n]; }
        float inv = 1.0f / sum;
        for (int n = 0; n < NK; n++) g_attn[t * NK + n] = e[n] * inv;
    }
}

// ---------------- Kernel 3: mix kernel bank ----------------
__global__ void mix_kernel(const float* __restrict__ bank) {
    const int R = C_OUT * C_IN * 9;
    int i = blockIdx.x * blockDim.x + threadIdx.x;
    if (i >= BB * R) return;
    int b = i / R, r = i - b * R;
    float s = 0.f;
    #pragma unroll
    for (int n = 0; n < NK; n++) s += g_attn[b * NK + n] * bank[(size_t)n * R + r];
    g_mixed[i] = s;
}

// ------- Kernel 3b: mixed weights -> fp16, [b][tap][co][ci] -------
__global__ void split_w_kernel() {
    int i = blockIdx.x * blockDim.x + threadIdx.x;   // over b*co*ci
    if (i >= BB * C_OUT * C_IN) return;
    int ci = i & 63;
    int co = (i >> 6) & 127;
    int b = i >> 13;
    const float* src = g_mixed + ((size_t)i) * 9;
    #pragma unroll
    for (int tap = 0; tap < 9; tap++) {
        size_t o = ((((size_t)b * 9 + tap) * C_OUT + co) * C_IN) + ci;
        g_w16[o] = __float2half(src[tap]);
    }
}

// ------- Kernel 3c: convert + transpose x -> [b][y][x][ci] fp16 -------
__global__ void __launch_bounds__(256) split_x_kernel(const float* __restrict__ x) {
    int y = blockIdx.x;
    int b = blockIdx.y;
    int xc = threadIdx.x;   // 0..255
    const float* xp = x + ((size_t)b * C_IN) * (HH * WW) + y * WW + xc;
    uint32_t h2[C_IN / 2];
    #pragma unroll
    for (int c = 0; c < C_IN; c += 2) {
        __half h0 = __float2half(xp[(size_t)c * (HH * WW)]);
        __half h1 = __float2half(xp[(size_t)(c + 1) * (HH * WW)]);
        h2[c / 2] = (uint32_t)__half_as_ushort(h0) |
                    ((uint32_t)__half_as_ushort(h1) << 16);
    }
    size_t o = (((size_t)b * HH + y) * WW + xc) * C_IN;
    uint4* dh = reinterpret_cast<uint4*>(g_x16 + o);
    #pragma unroll
    for (int j = 0; j < C_IN / 8; j++)
        dh[j] = make_uint4(h2[j * 4], h2[j * 4 + 1], h2[j * 4 + 2], h2[j * 4 + 3]);
}

// ---------------- Kernel 4: HMMA implicit-GEMM conv (pure fp16) ----------------
// CTA: 256 thr = 8 warps (2 M x 4 N). Tile M=128 pixels = 2 y-rows x 64 px,
// N=128 c_out, K = 9 taps x 64 ci, single fp16 term, fp32 accumulators.
// A staged ONCE; W prefetched per tap through a 2-stage cp.async ring
// (16B ops, loop-invariant addresses) so the LDG latency is off the
// critical path. smem = 74.9KB -> 3 CTAs/SM.
__global__ void __launch_bounds__(256, 3) conv_tc_kernel(float* __restrict__ out) {
    extern __shared__ __half smem[];
    __half* sA = smem;                          // [AROWS][APITCH]
    __half* sW = smem + AROWS * APITCH;         // [2][WROWS][APITCH]

    const int tid = threadIdx.x;
    const int lane = tid & 31;
    const int wid = tid >> 5;
    const int wm = wid >> 2;          // 0..1  (local y row)
    const int wn = wid & 3;           // 0..3  (N / c_out group)
    const int x0 = blockIdx.x * 64;
    const int y0 = blockIdx.y * 2;
    const int b = blockIdx.z;

    uint32_t sA_u32 = (uint32_t)__cvta_generic_to_shared(sA);
    uint32_t sW_u32 = (uint32_t)__cvta_generic_to_shared(sW);

    // ---- W prefetch plan: 1024 16B chunks per tap; 4 per thread ----
    // chunk k: row = k>>3 (co), sub = k&7. dst halfs offset = row*APITCH + sub*8.
    uint32_t w_dst[4];
    const __half* w_src[4];
    #pragma unroll
    for (int s = 0; s < 4; s++) {
        int k = tid + s * 256;
        int row = k >> 3, sub = k & 7;
        w_dst[s] = sW_u32 + (uint32_t)(row * APITCH + sub * 8) * 2;
        w_src[s] = g_w16 + ((size_t)(b * 9 + 0) * C_OUT + row) * C_IN + sub * 8;
    }
    const size_t W_TAP_STRIDE = (size_t)C_OUT * C_IN;   // halfs per tap
    const uint32_t W_BUF_STRIDE = WROWS * APITCH * 2;   // bytes per ring slot

    auto issue_w = [&](int tap) {
        uint32_t boff = (uint32_t)(tap & 1) * W_BUF_STRIDE;
        size_t goff = (size_t)tap * W_TAP_STRIDE;
        #pragma unroll
        for (int s = 0; s < 4; s++) cpasync16(w_dst[s] + boff, w_src[s] + goff);
    };

    // prologue: taps 0 and 1 in flight
    issue_w(0);
    cp_commit();
    issue_w(1);
    cp_commit();

    // ---- stage A: rows r = yblk*66 + xi ; (y0-1+yblk, x0-1+xi) ----
    const uint4 z4 = make_uint4(0, 0, 0, 0);
    for (int i = tid; i < AROWS; i += 256) {
        int yblk = i / 66, xi = i - yblk * 66;
        int yy = y0 - 1 + yblk;
        int xx = x0 + xi - 1;
        bool v = (yy >= 0) && (yy < HH) && (xx >= 0) && (xx < WW);
        const __half* gsrc = g_x16 +
            (((size_t)b * HH + (v ? yy : 0)) * WW + (v ? xx : 0)) * C_IN;
        const uint4* src = reinterpret_cast<const uint4*>(gsrc);
        uint4* dst = reinterpret_cast<uint4*>(sA + (size_t)i * APITCH);
        #pragma unroll
        for (int j = 0; j < 8; j++) dst[j] = v ? src[j] : z4;
    }

    float acc[4][4][4];
    #pragma unroll
    for (int mt = 0; mt < 4; mt++)
        #pragma unroll
        for (int nt = 0; nt < 4; nt++)
            #pragma unroll
            for (int q = 0; q < 4; q++) acc[mt][nt][q] = 0.f;

    const int row16_l = lane & 15;
    const int koff_l = (lane >> 4) * 16;   // bytes

    for (int tap = 0; tap < 9; tap++) {
        cp_wait1();        // group(tap) complete (groups tap, tap+1 pending at most)
        __syncthreads();   // all cp.async data + A tile (tap 0) visible to all warps

        const int dy = tap / 3 - 1, dx = tap % 3 - 1;
        const int arow0 = (wm + dy + 1) * 66 + (dx + 1);
        const uint32_t sWb = sW_u32 + (uint32_t)(tap & 1) * W_BUF_STRIDE;

        #pragma unroll
        for (int kc = 0; kc < 4; kc++) {
            const uint32_t kb = (uint32_t)(kc * 32 + koff_l);
            uint32_t ah[4][4];
            #pragma unroll
            for (int mt = 0; mt < 4; mt++) {
                uint32_t rowoff = (uint32_t)(arow0 + 16 * mt + row16_l) * 144 + kb;
                ldm_x4(ah[mt][0], ah[mt][1], ah[mt][2], ah[mt][3], sA_u32 + rowoff);
            }
            #pragma unroll
            for (int ntp = 0; ntp < 2; ntp++) {
                uint32_t browoff = (uint32_t)(32 * wn + 16 * ntp + row16_l) * 144 + kb;
                uint32_t h0, h1, h2, h3;
                ldm_x4(h0, h1, h2, h3, sWb + browoff);
                uint32_t bh0[2] = {h0, h2}, bh1[2] = {h1, h3};
                int nt0 = 2 * ntp, nt1 = 2 * ntp + 1;
                #pragma unroll
                for (int mt = 0; mt < 4; mt++) {
                    mma_fp16(acc[mt][nt0], ah[mt], bh0);
                    mma_fp16(acc[mt][nt1], ah[mt], bh1);
                }
            }
        }

        __syncthreads();   // all warps done reading buf (tap&1) before overwrite
        if (tap + 2 <= 8) issue_w(tap + 2);
        cp_commit();       // always commit (possibly empty) to keep group count uniform
    }

    // ---- epilogue: c-frag m16n8 layout -> out[b][co][y][px] ----
    const int gid = lane >> 2, qid = lane & 3;
    const int yo = y0 + wm;
    #pragma unroll
    for (int mt = 0; mt < 4; mt++) {
        int px0 = x0 + 16 * mt + gid;
        #pragma unroll
        for (int nt = 0; nt < 4; nt++) {
            int co0 = 32 * wn + 8 * nt + 2 * qid;
            float* c = acc[mt][nt];
            size_t o00 = (((size_t)b * C_OUT + co0) * HH + yo) * WW + px0;
            size_t o01 = o00 + (size_t)HH * WW;          // co0+1
            out[o00] = c[0];
            out[o01] = c[1];
            out[o00 + 8] = c[2];                          // px0+8
            out[o01 + 8] = c[3];
        }
    }
}

extern "C" void kernel_launch(void* const* d_in, const int* in_sizes, int n_in,
                              void* d_out, int out_size) {
    const float* x    = (const float*)d_in[0];
    const float* bank = (const float*)d_in[1];
    const float* aw   = (const float*)d_in[2];
    const float* ab   = (const float*)d_in[3];
    float* out = (float*)d_out;

    pool_kernel<<<BB * C_IN, 256>>>(x);
    attn_kernel<<<1, 64>>>(aw, ab);
    mix_kernel<<<(BB * C_OUT * C_IN * 9 + 255) / 256, 256>>>(bank);
    split_w_kernel<<<(BB * C_OUT * C_IN + 255) / 256, 256>>>();
    split_x_kernel<<<dim3(HH, BB), 256>>>(x);

    const int smem_bytes = (AROWS + 2 * WROWS) * APITCH * 2;  // 74,880 B
    cudaFuncSetAttribute(conv_tc_kernel,
                         cudaFuncAttributeMaxDynamicSharedMemorySize, smem_bytes);
    dim3 g(WW / 64, HH / 2, BB);
    conv_tc_kernel<<<g, 256, smem_bytes>>>(out);
}

// round 14
// speedup vs baseline: 4.3230x; 1.0968x over previous
#include <cuda_runtime.h>
#include <cuda_fp16.h>
#include <cstdint>

#define BB 8
#define C_IN 64
#define C_OUT 128
#define HH 256
#define WW 256
#define NK 8

#define APITCH 72            // fp16 elems per smem row (144B, conflict-free ldmatrix)
#define AROWS 264            // 4 y-blocks x 66 x-halo entries
#define WROWS 128

__device__ float g_pooled[BB * C_IN];
__device__ float g_attn[BB * NK];

// fp16 tensors: x transposed to [b][y][x][ci]; w [b][tap][co][ci]
__device__ __half g_x16[(size_t)BB * HH * WW * C_IN];
__device__ __half g_w16[(size_t)BB * 9 * C_OUT * C_IN];

// ---------------- portable tensor-core helpers (sm_80+ PTX) ----------------
__device__ __forceinline__ void ldm_x4(uint32_t& r0, uint32_t& r1, uint32_t& r2,
                                       uint32_t& r3, uint32_t addr) {
    asm volatile("ldmatrix.sync.aligned.m8n8.x4.shared.b16 {%0,%1,%2,%3}, [%4];"
                 : "=r"(r0), "=r"(r1), "=r"(r2), "=r"(r3) : "r"(addr));
}
__device__ __forceinline__ void mma_fp16(float* c, const uint32_t* a,
                                         const uint32_t* bfr) {
    asm volatile(
        "mma.sync.aligned.m16n8k16.row.col.f32.f16.f16.f32 "
        "{%0,%1,%2,%3}, {%4,%5,%6,%7}, {%8,%9}, {%0,%1,%2,%3};"
        : "+f"(c[0]), "+f"(c[1]), "+f"(c[2]), "+f"(c[3])
        : "r"(a[0]), "r"(a[1]), "r"(a[2]), "r"(a[3]), "r"(bfr[0]), "r"(bfr[1]));
}
__device__ __forceinline__ void cpasync16(uint32_t saddr, const void* g) {
    asm volatile("cp.async.cg.shared.global [%0], [%1], 16;"
                 :: "r"(saddr), "l"(g));
}
__device__ __forceinline__ void cpasync16z(uint32_t saddr, const void* g, int srcsz) {
    asm volatile("cp.async.cg.shared.global [%0], [%1], 16, %2;"
                 :: "r"(saddr), "l"(g), "r"(srcsz));
}
__device__ __forceinline__ void cp_commit() {
    asm volatile("cp.async.commit_group;");
}
__device__ __forceinline__ void cp_wait1() {
    asm volatile("cp.async.wait_group 1;");
}

// ---------------- Kernel 1: global average pool ----------------
__global__ void pool_kernel(const float* __restrict__ x) {
    int idx = blockIdx.x;  // b*C_IN + ci
    const float4* p = reinterpret_cast<const float4*>(x + (size_t)idx * (HH * WW));
    float s = 0.f;
    for (int i = threadIdx.x; i < (HH * WW) / 4; i += blockDim.x) {
        float4 v = p[i];
        s += v.x + v.y + v.z + v.w;
    }
    __shared__ float red[256];
    red[threadIdx.x] = s;
    __syncthreads();
    for (int off = 128; off > 0; off >>= 1) {
        if (threadIdx.x < off) red[threadIdx.x] += red[threadIdx.x + off];
        __syncthreads();
    }
    if (threadIdx.x == 0) g_pooled[idx] = red[0] * (1.0f / (HH * WW));
}

// ---------------- Kernel 2: logits + softmax ----------------
__global__ void attn_kernel(const float* __restrict__ attn_w,
                            const float* __restrict__ attn_b) {
    __shared__ float lg[BB * NK];
    int t = threadIdx.x;
    if (t < BB * NK) {
        int b = t / NK, n = t % NK;
        float s = attn_b[n];
        #pragma unroll 8
        for (int c = 0; c < C_IN; c++) s += g_pooled[b * C_IN + c] * attn_w[n * C_IN + c];
        lg[t] = s;
    }
    __syncthreads();
    if (t < BB) {
        float m = -1e30f;
        for (int n = 0; n < NK; n++) m = fmaxf(m, lg[t * NK + n]);
        float e[NK];
        float sum = 0.f;
        for (int n = 0; n < NK; n++) { e[n] = expf(lg[t * NK + n] - m); sum += e[n]; }
        float inv = 1.0f / sum;
        for (int n = 0; n < NK; n++) g_attn[t * NK + n] = e[n] * inv;
    }
}

// ------- Kernel 3: fused mix + fp16 convert, writes [b][tap][co][ci] -------
__global__ void mix_w_kernel(const float* __restrict__ bank) {
    int i = blockIdx.x * blockDim.x + threadIdx.x;   // over b*co*ci
    if (i >= BB * C_OUT * C_IN) return;
    int ci = i & 63;
    int co = (i >> 6) & 127;
    int b = i >> 13;
    float a[NK];
    #pragma unroll
    for (int n = 0; n < NK; n++) a[n] = g_attn[b * NK + n];
    const float* bk = bank + ((size_t)co * C_IN + ci) * 9;
    const size_t nstride = (size_t)C_OUT * C_IN * 9;
    #pragma unroll
    for (int tap = 0; tap < 9; tap++) {
        float s = 0.f;
        #pragma unroll
        for (int n = 0; n < NK; n++) s += a[n] * bk[n * nstride + tap];
        g_w16[((((size_t)b * 9 + tap) * C_OUT + co) * C_IN) + ci] = __float2half(s);
    }
}

// ------- Kernel 3c: convert + transpose x -> [b][y][x][ci] fp16 -------
__global__ void __launch_bounds__(256) split_x_kernel(const float* __restrict__ x) {
    int y = blockIdx.x;
    int b = blockIdx.y;
    int xc = threadIdx.x;   // 0..255
    const float* xp = x + ((size_t)b * C_IN) * (HH * WW) + y * WW + xc;
    uint32_t h2[C_IN / 2];
    #pragma unroll
    for (int c = 0; c < C_IN; c += 2) {
        __half h0 = __float2half(xp[(size_t)c * (HH * WW)]);
        __half h1 = __float2half(xp[(size_t)(c + 1) * (HH * WW)]);
        h2[c / 2] = (uint32_t)__half_as_ushort(h0) |
                    ((uint32_t)__half_as_ushort(h1) << 16);
    }
    size_t o = (((size_t)b * HH + y) * WW + xc) * C_IN;
    uint4* dh = reinterpret_cast<uint4*>(g_x16 + o);
    #pragma unroll
    for (int j = 0; j < C_IN / 8; j++)
        dh[j] = make_uint4(h2[j * 4], h2[j * 4 + 1], h2[j * 4 + 2], h2[j * 4 + 3]);
}

// ---------------- Kernel 4: HMMA implicit-GEMM conv (pure fp16) ----------------
// CTA: 256 thr = 8 warps (2 M x 4 N). Tile M=128 pixels = 2 y-rows x 64 px,
// N=128 c_out, K = 9 taps x 64 ci, single fp16 term, fp32 accumulators.
// A staged via cp.async (group 0, zfill for OOB); W per tap through a
// 2-stage cp.async ring. smem = 74.9KB -> 3 CTAs/SM.
__global__ void __launch_bounds__(256, 3) conv_tc_kernel(float* __restrict__ out) {
    extern __shared__ __half smem[];
    __half* sA = smem;                          // [AROWS][APITCH]
    __half* sW = smem + AROWS * APITCH;         // [2][WROWS][APITCH]

    const int tid = threadIdx.x;
    const int lane = tid & 31;
    const int wid = tid >> 5;
    const int wm = wid >> 2;          // 0..1  (local y row)
    const int wn = wid & 3;           // 0..3  (N / c_out group)
    const int x0 = blockIdx.x * 64;
    const int y0 = blockIdx.y * 2;
    const int b = blockIdx.z;

    uint32_t sA_u32 = (uint32_t)__cvta_generic_to_shared(sA);
    uint32_t sW_u32 = (uint32_t)__cvta_generic_to_shared(sW);

    // ---- stage A via cp.async (group 0): 264 rows x 8 16B chunks ----
    // chunk k: row = k>>3, sub = k&7; row = yblk*66 + xi
    for (int k = tid; k < AROWS * 8; k += 256) {
        int row = k >> 3, sub = k & 7;
        int yblk = row / 66, xi = row - yblk * 66;
        int yy = y0 - 1 + yblk;
        int xx = x0 + xi - 1;
        bool v = (yy >= 0) && (yy < HH) && (xx >= 0) && (xx < WW);
        const __half* gsrc = g_x16 +
            (((size_t)b * HH + (v ? yy : 0)) * WW + (v ? xx : 0)) * C_IN + sub * 8;
        cpasync16z(sA_u32 + (uint32_t)(row * APITCH + sub * 8) * 2, gsrc, v ? 16 : 0);
    }
    cp_commit();   // group: A

    // ---- W prefetch plan: 1024 16B chunks per tap; 4 per thread ----
    uint32_t w_dst[4];
    const __half* w_src[4];
    #pragma unroll
    for (int s = 0; s < 4; s++) {
        int k = tid + s * 256;
        int row = k >> 3, sub = k & 7;
        w_dst[s] = sW_u32 + (uint32_t)(row * APITCH + sub * 8) * 2;
        w_src[s] = g_w16 + ((size_t)(b * 9 + 0) * C_OUT + row) * C_IN + sub * 8;
    }
    const size_t W_TAP_STRIDE = (size_t)C_OUT * C_IN;   // halfs per tap
    const uint32_t W_BUF_STRIDE = WROWS * APITCH * 2;   // bytes per ring slot

    auto issue_w = [&](int tap) {
        uint32_t boff = (uint32_t)(tap & 1) * W_BUF_STRIDE;
        size_t goff = (size_t)tap * W_TAP_STRIDE;
        #pragma unroll
        for (int s = 0; s < 4; s++) cpasync16(w_dst[s] + boff, w_src[s] + goff);
    };

    issue_w(0);
    cp_commit();   // group: W0
    issue_w(1);
    cp_commit();   // group: W1

    float acc[4][4][4];
    #pragma unroll
    for (int mt = 0; mt < 4; mt++)
        #pragma unroll
        for (int nt = 0; nt < 4; nt++)
            #pragma unroll
            for (int q = 0; q < 4; q++) acc[mt][nt][q] = 0.f;

    const int row16_l = lane & 15;
    const int koff_l = (lane >> 4) * 16;   // bytes

    for (int tap = 0; tap < 9; tap++) {
        cp_wait1();        // at tap0: A + W0 complete; later: W(tap) complete
        __syncthreads();

        const int dy = tap / 3 - 1, dx = tap % 3 - 1;
        const int arow0 = (wm + dy + 1) * 66 + (dx + 1);
        const uint32_t sWb = sW_u32 + (uint32_t)(tap & 1) * W_BUF_STRIDE;

        #pragma unroll
        for (int kc = 0; kc < 4; kc++) {
            const uint32_t kb = (uint32_t)(kc * 32 + koff_l);
            uint32_t ah[4][4];
            #pragma unroll
            for (int mt = 0; mt < 4; mt++) {
                uint32_t rowoff = (uint32_t)(arow0 + 16 * mt + row16_l) * 144 + kb;
                ldm_x4(ah[mt][0], ah[mt][1], ah[mt][2], ah[mt][3], sA_u32 + rowoff);
            }
            #pragma unroll
            for (int ntp = 0; ntp < 2; ntp++) {
                uint32_t browoff = (uint32_t)(32 * wn + 16 * ntp + row16_l) * 144 + kb;
                uint32_t h0, h1, h2, h3;
                ldm_x4(h0, h1, h2, h3, sWb + browoff);
                uint32_t bh0[2] = {h0, h2}, bh1[2] = {h1, h3};
                int nt0 = 2 * ntp, nt1 = 2 * ntp + 1;
                #pragma unroll
                for (int mt = 0; mt < 4; mt++) {
                    mma_fp16(acc[mt][nt0], ah[mt], bh0);
                    mma_fp16(acc[mt][nt1], ah[mt], bh1);
                }
            }
        }

        __syncthreads();   // all warps done reading buf (tap&1) before overwrite
        if (tap + 2 <= 8) issue_w(tap + 2);
        cp_commit();       // always commit to keep group counting uniform
    }

    // ---- epilogue: c-frag m16n8 layout -> out[b][co][y][px] ----
    const int gid = lane >> 2, qid = lane & 3;
    const int yo = y0 + wm;
    #pragma unroll
    for (int mt = 0; mt < 4; mt++) {
        int px0 = x0 + 16 * mt + gid;
        #pragma unroll
        for (int nt = 0; nt < 4; nt++) {
            int co0 = 32 * wn + 8 * nt + 2 * qid;
            float* c = acc[mt][nt];
            size_t o00 = (((size_t)b * C_OUT + co0) * HH + yo) * WW + px0;
            size_t o01 = o00 + (size_t)HH * WW;          // co0+1
            out[o00] = c[0];
            out[o01] = c[1];
            out[o00 + 8] = c[2];                          // px0+8
            out[o01 + 8] = c[3];
        }
    }
}

extern "C" void kernel_launch(void* const* d_in, const int* in_sizes, int n_in,
                              void* d_out, int out_size) {
    const float* x    = (const float*)d_in[0];
    const float* bank = (const float*)d_in[1];
    const float* aw   = (const float*)d_in[2];
    const float* ab   = (const float*)d_in[3];
    float* out = (float*)d_out;

    pool_kernel<<<BB * C_IN, 256>>>(x);
    attn_kernel<<<1, 64>>>(aw, ab);
    mix_w_kernel<<<(BB * C_OUT * C_IN + 255) / 256, 256>>>(bank);
    split_x_kernel<<<dim3(HH, BB), 256>>>(x);

    const int smem_bytes = (AROWS + 2 * WROWS) * APITCH * 2;  // 74,880 B
    cudaFuncSetAttribute(conv_tc_kernel,
                         cudaFuncAttributeMaxDynamicSharedMemorySize, smem_bytes);
    dim3 g(WW / 64, HH / 2, BB);
    conv_tc_kernel<<<g, 256, smem_bytes>>>(out);
}

// round 15
// speedup vs baseline: 5.5766x; 1.2900x over previous
#include <cuda_runtime.h>
#include <cuda_fp16.h>
#include <cstdint>

#define BB 8
#define C_IN 64
#define C_OUT 128
#define HH 256
#define WW 256
#define NK 8

#define APITCH 72            // fp16 elems per smem row (144B, conflict-free ldmatrix)
#define AROWS 396            // 6 y-blocks x 66 x-halo entries
#define WROWS 128
#define CONV_THREADS 512

__device__ float g_pooled[BB * C_IN];
__device__ float g_attn[BB * NK];

// fp16 tensors: x transposed to [b][y][x][ci]; w [b][tap][co][ci]
__device__ __half g_x16[(size_t)BB * HH * WW * C_IN];
__device__ __half g_w16[(size_t)BB * 9 * C_OUT * C_IN];

// ---------------- portable tensor-core helpers (sm_80+ PTX) ----------------
__device__ __forceinline__ void ldm_x4(uint32_t& r0, uint32_t& r1, uint32_t& r2,
                                       uint32_t& r3, uint32_t addr) {
    asm volatile("ldmatrix.sync.aligned.m8n8.x4.shared.b16 {%0,%1,%2,%3}, [%4];"
                 : "=r"(r0), "=r"(r1), "=r"(r2), "=r"(r3) : "r"(addr));
}
__device__ __forceinline__ void mma_fp16(float* c, const uint32_t* a,
                                         const uint32_t* bfr) {
    asm volatile(
        "mma.sync.aligned.m16n8k16.row.col.f32.f16.f16.f32 "
        "{%0,%1,%2,%3}, {%4,%5,%6,%7}, {%8,%9}, {%0,%1,%2,%3};"
        : "+f"(c[0]), "+f"(c[1]), "+f"(c[2]), "+f"(c[3])
        : "r"(a[0]), "r"(a[1]), "r"(a[2]), "r"(a[3]), "r"(bfr[0]), "r"(bfr[1]));
}
__device__ __forceinline__ void cpasync16(uint32_t saddr, const void* g) {
    asm volatile("cp.async.cg.shared.global [%0], [%1], 16;"
                 :: "r"(saddr), "l"(g));
}
__device__ __forceinline__ void cpasync16z(uint32_t saddr, const void* g, int srcsz) {
    asm volatile("cp.async.cg.shared.global [%0], [%1], 16, %2;"
                 :: "r"(saddr), "l"(g), "r"(srcsz));
}
__device__ __forceinline__ void cp_commit() {
    asm volatile("cp.async.commit_group;");
}
__device__ __forceinline__ void cp_wait1() {
    asm volatile("cp.async.wait_group 1;");
}

// ---------------- Kernel 1: global average pool ----------------
__global__ void pool_kernel(const float* __restrict__ x) {
    int idx = blockIdx.x;  // b*C_IN + ci
    const float4* p = reinterpret_cast<const float4*>(x + (size_t)idx * (HH * WW));
    float s = 0.f;
    for (int i = threadIdx.x; i < (HH * WW) / 4; i += blockDim.x) {
        float4 v = p[i];
        s += v.x + v.y + v.z + v.w;
    }
    __shared__ float red[256];
    red[threadIdx.x] = s;
    __syncthreads();
    for (int off = 128; off > 0; off >>= 1) {
        if (threadIdx.x < off) red[threadIdx.x] += red[threadIdx.x + off];
        __syncthreads();
    }
    if (threadIdx.x == 0) g_pooled[idx] = red[0] * (1.0f / (HH * WW));
}

// ---------------- Kernel 2: logits + softmax ----------------
__global__ void attn_kernel(const float* __restrict__ attn_w,
                            const float* __restrict__ attn_b) {
    __shared__ float lg[BB * NK];
    int t = threadIdx.x;
    if (t < BB * NK) {
        int b = t / NK, n = t % NK;
        float s = attn_b[n];
        #pragma unroll 8
        for (int c = 0; c < C_IN; c++) s += g_pooled[b * C_IN + c] * attn_w[n * C_IN + c];
        lg[t] = s;
    }
    __syncthreads();
    if (t < BB) {
        float m = -1e30f;
        for (int n = 0; n < NK; n++) m = fmaxf(m, lg[t * NK + n]);
        float e[NK];
        float sum = 0.f;
        for (int n = 0; n < NK; n++) { e[n] = expf(lg[t * NK + n] - m); sum += e[n]; }
        float inv = 1.0f / sum;
        for (int n = 0; n < NK; n++) g_attn[t * NK + n] = e[n] * inv;
    }
}

// ------- Kernel 3: fused mix + fp16 convert, writes [b][tap][co][ci] -------
__global__ void mix_w_kernel(const float* __restrict__ bank) {
    int i = blockIdx.x * blockDim.x + threadIdx.x;   // over b*co*ci
    if (i >= BB * C_OUT * C_IN) return;
    int ci = i & 63;
    int co = (i >> 6) & 127;
    int b = i >> 13;
    float a[NK];
    #pragma unroll
    for (int n = 0; n < NK; n++) a[n] = g_attn[b * NK + n];
    const float* bk = bank + ((size_t)co * C_IN + ci) * 9;
    const size_t nstride = (size_t)C_OUT * C_IN * 9;
    #pragma unroll
    for (int tap = 0; tap < 9; tap++) {
        float s = 0.f;
        #pragma unroll
        for (int n = 0; n < NK; n++) s += a[n] * bk[n * nstride + tap];
        g_w16[((((size_t)b * 9 + tap) * C_OUT + co) * C_IN) + ci] = __float2half(s);
    }
}

// ------- Kernel 3c: convert + transpose x -> [b][y][x][ci] fp16 -------
__global__ void __launch_bounds__(256) split_x_kernel(const float* __restrict__ x) {
    int y = blockIdx.x;
    int b = blockIdx.y;
    int xc = threadIdx.x;   // 0..255
    const float* xp = x + ((size_t)b * C_IN) * (HH * WW) + y * WW + xc;
    uint32_t h2[C_IN / 2];
    #pragma unroll
    for (int c = 0; c < C_IN; c += 2) {
        __half h0 = __float2half(xp[(size_t)c * (HH * WW)]);
        __half h1 = __float2half(xp[(size_t)(c + 1) * (HH * WW)]);
        h2[c / 2] = (uint32_t)__half_as_ushort(h0) |
                    ((uint32_t)__half_as_ushort(h1) << 16);
    }
    size_t o = (((size_t)b * HH + y) * WW + xc) * C_IN;
    uint4* dh = reinterpret_cast<uint4*>(g_x16 + o);
    #pragma unroll
    for (int j = 0; j < C_IN / 8; j++)
        dh[j] = make_uint4(h2[j * 4], h2[j * 4 + 1], h2[j * 4 + 2], h2[j * 4 + 3]);
}

// ---------------- Kernel 4: HMMA implicit-GEMM conv (pure fp16) ----------------
// CTA: 512 thr = 16 warps (4 M x 4 N). Tile M=256 pixels = 4 y-rows x 64 px,
// N=128 c_out, K = 9 taps x 64 ci, single fp16 term, fp32 accumulators.
// A staged via cp.async (group 0, zfill OOB); W per tap through a 2-stage
// cp.async ring. smem = 93.9KB; 1 CTA/SM (reg-capped), 16 warps.
__global__ void __launch_bounds__(CONV_THREADS, 1) conv_tc_kernel(float* __restrict__ out) {
    extern __shared__ __half smem[];
    __half* sA = smem;                          // [AROWS][APITCH]
    __half* sW = smem + AROWS * APITCH;         // [2][WROWS][APITCH]

    const int tid = threadIdx.x;
    const int lane = tid & 31;
    const int wid = tid >> 5;
    const int wm = wid >> 2;          // 0..3  (local y row)
    const int wn = wid & 3;           // 0..3  (N / c_out group)
    const int x0 = blockIdx.x * 64;
    const int y0 = blockIdx.y * 4;
    const int b = blockIdx.z;

    uint32_t sA_u32 = (uint32_t)__cvta_generic_to_shared(sA);
    uint32_t sW_u32 = (uint32_t)__cvta_generic_to_shared(sW);

    // ---- stage A via cp.async (group 0): 396 rows x 8 16B chunks ----
    for (int k = tid; k < AROWS * 8; k += CONV_THREADS) {
        int row = k >> 3, sub = k & 7;
        int yblk = row / 66, xi = row - yblk * 66;
        int yy = y0 - 1 + yblk;
        int xx = x0 + xi - 1;
        bool v = (yy >= 0) && (yy < HH) && (xx >= 0) && (xx < WW);
        const __half* gsrc = g_x16 +
            (((size_t)b * HH + (v ? yy : 0)) * WW + (v ? xx : 0)) * C_IN + sub * 8;
        cpasync16z(sA_u32 + (uint32_t)(row * APITCH + sub * 8) * 2, gsrc, v ? 16 : 0);
    }
    cp_commit();   // group: A

    // ---- W prefetch plan: 1024 16B chunks per tap; 2 per thread ----
    uint32_t w_dst[2];
    const __half* w_src[2];
    #pragma unroll
    for (int s = 0; s < 2; s++) {
        int k = tid + s * CONV_THREADS;
        int row = k >> 3, sub = k & 7;
        w_dst[s] = sW_u32 + (uint32_t)(row * APITCH + sub * 8) * 2;
        w_src[s] = g_w16 + ((size_t)(b * 9 + 0) * C_OUT + row) * C_IN + sub * 8;
    }
    const size_t W_TAP_STRIDE = (size_t)C_OUT * C_IN;   // halfs per tap
    const uint32_t W_BUF_STRIDE = WROWS * APITCH * 2;   // bytes per ring slot

    auto issue_w = [&](int tap) {
        uint32_t boff = (uint32_t)(tap & 1) * W_BUF_STRIDE;
        size_t goff = (size_t)tap * W_TAP_STRIDE;
        #pragma unroll
        for (int s = 0; s < 2; s++) cpasync16(w_dst[s] + boff, w_src[s] + goff);
    };

    issue_w(0);
    cp_commit();   // group: W0
    issue_w(1);
    cp_commit();   // group: W1

    float acc[4][4][4];
    #pragma unroll
    for (int mt = 0; mt < 4; mt++)
        #pragma unroll
        for (int nt = 0; nt < 4; nt++)
            #pragma unroll
            for (int q = 0; q < 4; q++) acc[mt][nt][q] = 0.f;

    const int row16_l = lane & 15;
    const int koff_l = (lane >> 4) * 16;   // bytes

    for (int tap = 0; tap < 9; tap++) {
        cp_wait1();        // at tap0: A + W0 complete; later: W(tap) complete
        __syncthreads();

        const int dy = tap / 3 - 1, dx = tap % 3 - 1;
        const int arow0 = (wm + dy + 1) * 66 + (dx + 1);
        const uint32_t sWb = sW_u32 + (uint32_t)(tap & 1) * W_BUF_STRIDE;

        #pragma unroll
        for (int kc = 0; kc < 4; kc++) {
            const uint32_t kb = (uint32_t)(kc * 32 + koff_l);
            uint32_t ah[4][4];
            #pragma unroll
            for (int mt = 0; mt < 4; mt++) {
                uint32_t rowoff = (uint32_t)(arow0 + 16 * mt + row16_l) * 144 + kb;
                ldm_x4(ah[mt][0], ah[mt][1], ah[mt][2], ah[mt][3], sA_u32 + rowoff);
            }
            #pragma unroll
            for (int ntp = 0; ntp < 2; ntp++) {
                uint32_t browoff = (uint32_t)(32 * wn + 16 * ntp + row16_l) * 144 + kb;
                uint32_t h0, h1, h2, h3;
                ldm_x4(h0, h1, h2, h3, sWb + browoff);
                uint32_t bh0[2] = {h0, h2}, bh1[2] = {h1, h3};
                int nt0 = 2 * ntp, nt1 = 2 * ntp + 1;
                #pragma unroll
                for (int mt = 0; mt < 4; mt++) {
                    mma_fp16(acc[mt][nt0], ah[mt], bh0);
                    mma_fp16(acc[mt][nt1], ah[mt], bh1);
                }
            }
        }

        __syncthreads();   // all warps done reading buf (tap&1) before overwrite
        if (tap + 2 <= 8) issue_w(tap + 2);
        cp_commit();       // always commit to keep group counting uniform
    }

    // ---- epilogue: c-frag m16n8 layout -> out[b][co][y][px] ----
    const int gid = lane >> 2, qid = lane & 3;
    const int yo = y0 + wm;
    #pragma unroll
    for (int mt = 0; mt < 4; mt++) {
        int px0 = x0 + 16 * mt + gid;
        #pragma unroll
        for (int nt = 0; nt < 4; nt++) {
            int co0 = 32 * wn + 8 * nt + 2 * qid;
            float* c = acc[mt][nt];
            size_t o00 = (((size_t)b * C_OUT + co0) * HH + yo) * WW + px0;
            size_t o01 = o00 + (size_t)HH * WW;          // co0+1
            out[o00] = c[0];
            out[o01] = c[1];
            out[o00 + 8] = c[2];                          // px0+8
            out[o01 + 8] = c[3];
        }
    }
}

extern "C" void kernel_launch(void* const* d_in, const int* in_sizes, int n_in,
                              void* d_out, int out_size) {
    const float* x    = (const float*)d_in[0];
    const float* bank = (const float*)d_in[1];
    const float* aw   = (const float*)d_in[2];
    const float* ab   = (const float*)d_in[3];
    float* out = (float*)d_out;

    pool_kernel<<<BB * C_IN, 256>>>(x);
    attn_kernel<<<1, 64>>>(aw, ab);
    mix_w_kernel<<<(BB * C_OUT * C_IN + 255) / 256, 256>>>(bank);
    split_x_kernel<<<dim3(HH, BB), 256>>>(x);

    const int smem_bytes = (AROWS + 2 * WROWS) * APITCH * 2;  // 93,888 B
    cudaFuncSetAttribute(conv_tc_kernel,
                         cudaFuncAttributeMaxDynamicSharedMemorySize, smem_bytes);
    dim3 g(WW / 64, HH / 4, BB);
    conv_tc_kernel<<<g, CONV_THREADS, smem_bytes>>>(out);
}

// round 16
// speedup vs baseline: 5.8010x; 1.0402x over previous
#include <cuda_runtime.h>
#include <cuda_fp16.h>
#include <cstdint>

#define BB 8
#define C_IN 64
#define C_OUT 128
#define HH 256
#define WW 256
#define NK 8

#define APITCH 72            // fp16 elems per smem row (144B, conflict-free ldmatrix)
#define AROWS 396            // 6 y-blocks x 66 x-halo entries
#define WROWS 128
#define CONV_THREADS 512
#define YT 16                // y rows per split_x_pool block

__device__ float g_ppart[BB * 16 * C_IN];   // per-(b,ytile) channel sums
__device__ float g_attn[BB * NK];

// fp16 tensors: x transposed to [b][y][x][ci]; w [b][tap][co][ci]
__device__ __half g_x16[(size_t)BB * HH * WW * C_IN];
__device__ __half g_w16[(size_t)BB * 9 * C_OUT * C_IN];

// ---------------- portable tensor-core helpers (sm_80+ PTX) ----------------
__device__ __forceinline__ void ldm_x4(uint32_t& r0, uint32_t& r1, uint32_t& r2,
                                       uint32_t& r3, uint32_t addr) {
    asm volatile("ldmatrix.sync.aligned.m8n8.x4.shared.b16 {%0,%1,%2,%3}, [%4];"
                 : "=r"(r0), "=r"(r1), "=r"(r2), "=r"(r3) : "r"(addr));
}
__device__ __forceinline__ void mma_fp16(float* c, const uint32_t* a,
                                         const uint32_t* bfr) {
    asm volatile(
        "mma.sync.aligned.m16n8k16.row.col.f32.f16.f16.f32 "
        "{%0,%1,%2,%3}, {%4,%5,%6,%7}, {%8,%9}, {%0,%1,%2,%3};"
        : "+f"(c[0]), "+f"(c[1]), "+f"(c[2]), "+f"(c[3])
        : "r"(a[0]), "r"(a[1]), "r"(a[2]), "r"(a[3]), "r"(bfr[0]), "r"(bfr[1]));
}
__device__ __forceinline__ void cpasync16(uint32_t saddr, const void* g) {
    asm volatile("cp.async.cg.shared.global [%0], [%1], 16;"
                 :: "r"(saddr), "l"(g));
}
__device__ __forceinline__ void cpasync16z(uint32_t saddr, const void* g, int srcsz) {
    asm volatile("cp.async.cg.shared.global [%0], [%1], 16, %2;"
                 :: "r"(saddr), "l"(g), "r"(srcsz));
}
__device__ __forceinline__ void cp_commit() {
    asm volatile("cp.async.commit_group;");
}
__device__ __forceinline__ void cp_wait1() {
    asm volatile("cp.async.wait_group 1;");
}

// ------- Kernel 1: fused x convert/transpose + partial pooling -------
// Block = (ytile, b), 256 threads (one per x column). Each thread converts
// 16 rows x 64 channels to fp16 [b][y][x][ci] while accumulating per-channel
// sums in registers; block then shuffle-reduces and writes g_ppart[b][yt][ci].
__global__ void __launch_bounds__(256) split_x_pool_kernel(const float* __restrict__ x) {
    int yt = blockIdx.x;
    int b = blockIdx.y;
    int xc = threadIdx.x;
    int lane = xc & 31, wrp = xc >> 5;

    float s[C_IN];
    #pragma unroll
    for (int c = 0; c < C_IN; c++) s[c] = 0.f;

    for (int yy = 0; yy < YT; yy++) {
        int y = yt * YT + yy;
        const float* xp = x + ((size_t)b * C_IN) * (HH * WW) + y * WW + xc;
        uint32_t h2[C_IN / 2];
        #pragma unroll
        for (int c = 0; c < C_IN; c += 2) {
            float v0 = xp[(size_t)c * (HH * WW)];
            float v1 = xp[(size_t)(c + 1) * (HH * WW)];
            s[c] += v0;
            s[c + 1] += v1;
            __half h0 = __float2half(v0);
            __half h1 = __float2half(v1);
            h2[c / 2] = (uint32_t)__half_as_ushort(h0) |
                        ((uint32_t)__half_as_ushort(h1) << 16);
        }
        size_t o = (((size_t)b * HH + y) * WW + xc) * C_IN;
        uint4* dh = reinterpret_cast<uint4*>(g_x16 + o);
        #pragma unroll
        for (int j = 0; j < C_IN / 8; j++)
            dh[j] = make_uint4(h2[j * 4], h2[j * 4 + 1], h2[j * 4 + 2], h2[j * 4 + 3]);
    }

    // block reduce: warp shuffle per channel, then cross-warp via smem
    __shared__ float red[8][C_IN];
    #pragma unroll
    for (int c = 0; c < C_IN; c++) {
        float v = s[c];
        #pragma unroll
        for (int o = 16; o > 0; o >>= 1) v += __shfl_xor_sync(0xFFFFFFFFu, v, o);
        if (lane == 0) red[wrp][c] = v;
    }
    __syncthreads();
    if (xc < C_IN) {
        float p = 0.f;
        #pragma unroll
        for (int w2 = 0; w2 < 8; w2++) p += red[w2][xc];
        g_ppart[(b * 16 + yt) * C_IN + xc] = p;
    }
}

// ---------------- Kernel 2: finish pool + logits + softmax ----------------
__global__ void __launch_bounds__(512) attn_kernel(const float* __restrict__ attn_w,
                                                   const float* __restrict__ attn_b) {
    __shared__ float pooled[BB * C_IN];
    __shared__ float lg[BB * NK];
    int t = threadIdx.x;
    {
        int b = t >> 6, ci = t & 63;
        float p = 0.f;
        #pragma unroll
        for (int yt = 0; yt < 16; yt++) p += g_ppart[(b * 16 + yt) * C_IN + ci];
        pooled[t] = p * (1.0f / (HH * WW));
    }
    __syncthreads();
    if (t < BB * NK) {
        int b = t / NK, n = t % NK;
        float s = attn_b[n];
        #pragma unroll 8
        for (int c = 0; c < C_IN; c++) s += pooled[b * C_IN + c] * attn_w[n * C_IN + c];
        lg[t] = s;
    }
    __syncthreads();
    if (t < BB) {
        float m = -1e30f;
        for (int n = 0; n < NK; n++) m = fmaxf(m, lg[t * NK + n]);
        float e[NK];
        float sum = 0.f;
        for (int n = 0; n < NK; n++) { e[n] = expf(lg[t * NK + n] - m); sum += e[n]; }
        float inv = 1.0f / sum;
        for (int n = 0; n < NK; n++) g_attn[t * NK + n] = e[n] * inv;
    }
}

// ------- Kernel 3: fused mix + fp16 convert, bank read ONCE (all b per thread) ----
__global__ void mix_w_kernel(const float* __restrict__ bank) {
    int i = blockIdx.x * blockDim.x + threadIdx.x;   // over co*ci
    if (i >= C_OUT * C_IN) return;
    int ci = i & 63;
    int co = i >> 6;
    const size_t nstride = (size_t)C_OUT * C_IN * 9;
    const float* bk = bank + ((size_t)co * C_IN + ci) * 9;
    float bkr[NK][9];
    #pragma unroll
    for (int n = 0; n < NK; n++)
        #pragma unroll
        for (int tap = 0; tap < 9; tap++) bkr[n][tap] = bk[n * nstride + tap];
    #pragma unroll
    for (int b = 0; b < BB; b++) {
        float a[NK];
        #pragma unroll
        for (int n = 0; n < NK; n++) a[n] = g_attn[b * NK + n];
        #pragma unroll
        for (int tap = 0; tap < 9; tap++) {
            float s = 0.f;
            #pragma unroll
            for (int n = 0; n < NK; n++) s += a[n] * bkr[n][tap];
            g_w16[((((size_t)b * 9 + tap) * C_OUT + co) * C_IN) + ci] = __float2half(s);
        }
    }
}

// ---------------- Kernel 4: HMMA implicit-GEMM conv (pure fp16) ----------------
// CTA: 512 thr = 16 warps (4 M x 4 N). Tile M=256 pixels = 4 y-rows x 64 px,
// N=128 c_out, K = 9 taps x 64 ci, single fp16 term, fp32 accumulators.
// A staged via cp.async (group 0, zfill OOB); W per tap through a 2-stage
// cp.async ring. smem = 93.9KB; 1 CTA/SM (reg-capped), 16 warps.
__global__ void __launch_bounds__(CONV_THREADS, 1) conv_tc_kernel(float* __restrict__ out) {
    extern __shared__ __half smem[];
    __half* sA = smem;                          // [AROWS][APITCH]
    __half* sW = smem + AROWS * APITCH;         // [2][WROWS][APITCH]

    const int tid = threadIdx.x;
    const int lane = tid & 31;
    const int wid = tid >> 5;
    const int wm = wid >> 2;          // 0..3  (local y row)
    const int wn = wid & 3;           // 0..3  (N / c_out group)
    const int x0 = blockIdx.x * 64;
    const int y0 = blockIdx.y * 4;
    const int b = blockIdx.z;

    uint32_t sA_u32 = (uint32_t)__cvta_generic_to_shared(sA);
    uint32_t sW_u32 = (uint32_t)__cvta_generic_to_shared(sW);

    // ---- stage A via cp.async (group 0): 396 rows x 8 16B chunks ----
    for (int k = tid; k < AROWS * 8; k += CONV_THREADS) {
        int row = k >> 3, sub = k & 7;
        int yblk = row / 66, xi = row - yblk * 66;
        int yy = y0 - 1 + yblk;
        int xx = x0 + xi - 1;
        bool v = (yy >= 0) && (yy < HH) && (xx >= 0) && (xx < WW);
        const __half* gsrc = g_x16 +
            (((size_t)b * HH + (v ? yy : 0)) * WW + (v ? xx : 0)) * C_IN + sub * 8;
        cpasync16z(sA_u32 + (uint32_t)(row * APITCH + sub * 8) * 2, gsrc, v ? 16 : 0);
    }
    cp_commit();   // group: A

    // ---- W prefetch plan: 1024 16B chunks per tap; 2 per thread ----
    uint32_t w_dst[2];
    const __half* w_src[2];
    #pragma unroll
    for (int s = 0; s < 2; s++) {
        int k = tid + s * CONV_THREADS;
        int row = k >> 3, sub = k & 7;
        w_dst[s] = sW_u32 + (uint32_t)(row * APITCH + sub * 8) * 2;
        w_src[s] = g_w16 + ((size_t)(b * 9 + 0) * C_OUT + row) * C_IN + sub * 8;
    }
    const size_t W_TAP_STRIDE = (size_t)C_OUT * C_IN;   // halfs per tap
    const uint32_t W_BUF_STRIDE = WROWS * APITCH * 2;   // bytes per ring slot

    auto issue_w = [&](int tap) {
        uint32_t boff = (uint32_t)(tap & 1) * W_BUF_STRIDE;
        size_t goff = (size_t)tap * W_TAP_STRIDE;
        #pragma unroll
        for (int s = 0; s < 2; s++) cpasync16(w_dst[s] + boff, w_src[s] + goff);
    };

    issue_w(0);
    cp_commit();   // group: W0
    issue_w(1);
    cp_commit();   // group: W1

    float acc[4][4][4];
    #pragma unroll
    for (int mt = 0; mt < 4; mt++)
        #pragma unroll
        for (int nt = 0; nt < 4; nt++)
            #pragma unroll
            for (int q = 0; q < 4; q++) acc[mt][nt][q] = 0.f;

    const int row16_l = lane & 15;
    const int koff_l = (lane >> 4) * 16;   // bytes

    for (int tap = 0; tap < 9; tap++) {
        cp_wait1();        // at tap0: A + W0 complete; later: W(tap) complete
        __syncthreads();

        const int dy = tap / 3 - 1, dx = tap % 3 - 1;
        const int arow0 = (wm + dy + 1) * 66 + (dx + 1);
        const uint32_t sWb = sW_u32 + (uint32_t)(tap & 1) * W_BUF_STRIDE;

        #pragma unroll
        for (int kc = 0; kc < 4; kc++) {
            const uint32_t kb = (uint32_t)(kc * 32 + koff_l);
            uint32_t ah[4][4];
            #pragma unroll
            for (int mt = 0; mt < 4; mt++) {
                uint32_t rowoff = (uint32_t)(arow0 + 16 * mt + row16_l) * 144 + kb;
                ldm_x4(ah[mt][0], ah[mt][1], ah[mt][2], ah[mt][3], sA_u32 + rowoff);
            }
            #pragma unroll
            for (int ntp = 0; ntp < 2; ntp++) {
                uint32_t browoff = (uint32_t)(32 * wn + 16 * ntp + row16_l) * 144 + kb;
                uint32_t h0, h1, h2, h3;
                ldm_x4(h0, h1, h2, h3, sWb + browoff);
                uint32_t bh0[2] = {h0, h2}, bh1[2] = {h1, h3};
                int nt0 = 2 * ntp, nt1 = 2 * ntp + 1;
                #pragma unroll
                for (int mt = 0; mt < 4; mt++) {
                    mma_fp16(acc[mt][nt0], ah[mt], bh0);
                    mma_fp16(acc[mt][nt1], ah[mt], bh1);
                }
            }
        }

        __syncthreads();   // all warps done reading buf (tap&1) before overwrite
        if (tap + 2 <= 8) issue_w(tap + 2);
        cp_commit();       // always commit to keep group counting uniform
    }

    // ---- epilogue: c-frag m16n8 layout -> out[b][co][y][px] ----
    const int gid = lane >> 2, qid = lane & 3;
    const int yo = y0 + wm;
    #pragma unroll
    for (int mt = 0; mt < 4; mt++) {
        int px0 = x0 + 16 * mt + gid;
        #pragma unroll
        for (int nt = 0; nt < 4; nt++) {
            int co0 = 32 * wn + 8 * nt + 2 * qid;
            float* c = acc[mt][nt];
            size_t o00 = (((size_t)b * C_OUT + co0) * HH + yo) * WW + px0;
            size_t o01 = o00 + (size_t)HH * WW;          // co0+1
            out[o00] = c[0];
            out[o01] = c[1];
            out[o00 + 8] = c[2];                          // px0+8
            out[o01 + 8] = c[3];
        }
    }
}

extern "C" void kernel_launch(void* const* d_in, const int* in_sizes, int n_in,
                              void* d_out, int out_size) {
    const float* x    = (const float*)d_in[0];
    const float* bank = (const float*)d_in[1];
    const float* aw   = (const float*)d_in[2];
    const float* ab   = (const float*)d_in[3];
    float* out = (float*)d_out;

    split_x_pool_kernel<<<dim3(16, BB), 256>>>(x);
    attn_kernel<<<1, 512>>>(aw, ab);
    mix_w_kernel<<<(C_OUT * C_IN + 255) / 256, 256>>>(bank);

    const int smem_bytes = (AROWS + 2 * WROWS) * APITCH * 2;  // 93,888 B
    cudaFuncSetAttribute(conv_tc_kernel,
                         cudaFuncAttributeMaxDynamicSharedMemorySize, smem_bytes);
    dim3 g(WW / 64, HH / 4, BB);
    conv_tc_kernel<<<g, CONV_THREADS, smem_bytes>>>(out);
}